// round 1
// baseline (speedup 1.0000x reference)
#include <cuda_runtime.h>

// ---------------- problem constants ----------------
constexpr int BATCH = 2;
constexpr int SEQ   = 2048;
constexpr int DM    = 2048;   // d_model
constexpr int NH    = 16;     // heads
constexpr int HD    = 128;    // head dim
constexpr int NHD   = NH * HD; // 2048
constexpr float SCALE = 0.08838834764831845f; // 1/sqrt(128)

// ---------------- scratch (device globals; no allocations allowed) --------
__device__ float g_Q[(size_t)BATCH * NH * SEQ * HD];   // [B,N,S,H]
__device__ float g_K[(size_t)BATCH * NH * SEQ * HD];   // [B,N,S,H]
__device__ float g_V[(size_t)BATCH * NH * SEQ * HD];   // [B,N,S,H]
__device__ float g_ATT[(size_t)BATCH * SEQ * NH * HD]; // [B,S,N,H]
__device__ float g_q1[BATCH * NH * HD];
__device__ float g_k1[BATCH * NH * HD];
__device__ float g_v1[BATCH * NH * HD];
__device__ float g_att1[BATCH * NH * HD];

// ============================================================
// Projection GEMM:  out[b,n,s,h] = sum_d x[b,s,d] * w[d, n*H+h]
// x: [B*S, DM] row-major;  w: [DM, NHD] row-major.
// 128x128 tile, 256 threads, 8x8 per thread, K-step 8.
// sel: 0 -> g_Q, 1 -> g_K, 2 -> g_V
// ============================================================
__global__ __launch_bounds__(256) void proj_kernel(const float* __restrict__ x,
                                                   const float* __restrict__ w,
                                                   int sel) {
    __shared__ float As[8][128];
    __shared__ float Bs[8][128];

    float* out = (sel == 0) ? g_Q : ((sel == 1) ? g_K : g_V);

    const int tid  = threadIdx.x;
    const int row0 = blockIdx.y * 128;
    const int col0 = blockIdx.x * 128;
    const int tr = tid >> 4;      // 0..15
    const int tc = tid & 15;      // 0..15

    const int lr = tid >> 1;           // A load row (0..127)
    const int lk = (tid & 1) * 4;      // A load k   (0 or 4)
    const int bk = tid >> 5;           // B load k   (0..7)
    const int bc = (tid & 31) * 4;     // B load col (0..124)

    float acc[8][8];
#pragma unroll
    for (int i = 0; i < 8; i++)
#pragma unroll
        for (int j = 0; j < 8; j++) acc[i][j] = 0.f;

    for (int k0 = 0; k0 < DM; k0 += 8) {
        float4 av = *(const float4*)(x + (size_t)(row0 + lr) * DM + k0 + lk);
        As[lk + 0][lr] = av.x;
        As[lk + 1][lr] = av.y;
        As[lk + 2][lr] = av.z;
        As[lk + 3][lr] = av.w;
        *(float4*)&Bs[bk][bc] =
            *(const float4*)(w + (size_t)(k0 + bk) * NHD + col0 + bc);
        __syncthreads();

#pragma unroll
        for (int kk = 0; kk < 8; kk++) {
            float4 a0 = *(float4*)&As[kk][tr * 8];
            float4 a1 = *(float4*)&As[kk][tr * 8 + 4];
            float4 b0 = *(float4*)&Bs[kk][tc * 8];
            float4 b1 = *(float4*)&Bs[kk][tc * 8 + 4];
            float a[8] = {a0.x, a0.y, a0.z, a0.w, a1.x, a1.y, a1.z, a1.w};
            float bb[8] = {b0.x, b0.y, b0.z, b0.w, b1.x, b1.y, b1.z, b1.w};
#pragma unroll
            for (int i = 0; i < 8; i++)
#pragma unroll
                for (int j = 0; j < 8; j++) acc[i][j] += a[i] * bb[j];
        }
        __syncthreads();
    }

    // store: [B,N,S,H]
#pragma unroll
    for (int i = 0; i < 8; i++) {
        int gr = row0 + tr * 8 + i;           // b*SEQ + s
        int b = gr >> 11;
        int s = gr & (SEQ - 1);
#pragma unroll
        for (int j = 0; j < 8; j++) {
            int gc = col0 + tc * 8 + j;       // n*HD + h
            int n = gc >> 7;
            int h = gc & 127;
            out[(((size_t)b * NH + n) * SEQ + s) * HD + h] = acc[i][j];
        }
    }
}

// ============================================================
// Output projection (NT GEMM): out[row, d] = sum_k A[row,k] * wo[d,k]
// A = g_ATT [B*S, NHD] row-major; wo [DM, NHD] row-major.
// ============================================================
__global__ __launch_bounds__(256) void outproj_kernel(const float* __restrict__ wo,
                                                      float* __restrict__ out) {
    __shared__ float As[8][128];
    __shared__ float Bs[8][128];

    const float* A = g_ATT;

    const int tid  = threadIdx.x;
    const int row0 = blockIdx.y * 128;
    const int col0 = blockIdx.x * 128;
    const int tr = tid >> 4;
    const int tc = tid & 15;

    const int lr = tid >> 1;
    const int lk = (tid & 1) * 4;

    float acc[8][8];
#pragma unroll
    for (int i = 0; i < 8; i++)
#pragma unroll
        for (int j = 0; j < 8; j++) acc[i][j] = 0.f;

    for (int k0 = 0; k0 < NHD; k0 += 8) {
        float4 av = *(const float4*)(A + (size_t)(row0 + lr) * NHD + k0 + lk);
        As[lk + 0][lr] = av.x;
        As[lk + 1][lr] = av.y;
        As[lk + 2][lr] = av.z;
        As[lk + 3][lr] = av.w;
        float4 bv = *(const float4*)(wo + (size_t)(col0 + lr) * NHD + k0 + lk);
        Bs[lk + 0][lr] = bv.x;
        Bs[lk + 1][lr] = bv.y;
        Bs[lk + 2][lr] = bv.z;
        Bs[lk + 3][lr] = bv.w;
        __syncthreads();

#pragma unroll
        for (int kk = 0; kk < 8; kk++) {
            float4 a0 = *(float4*)&As[kk][tr * 8];
            float4 a1 = *(float4*)&As[kk][tr * 8 + 4];
            float4 b0 = *(float4*)&Bs[kk][tc * 8];
            float4 b1 = *(float4*)&Bs[kk][tc * 8 + 4];
            float a[8] = {a0.x, a0.y, a0.z, a0.w, a1.x, a1.y, a1.z, a1.w};
            float bb[8] = {b0.x, b0.y, b0.z, b0.w, b1.x, b1.y, b1.z, b1.w};
#pragma unroll
            for (int i = 0; i < 8; i++)
#pragma unroll
                for (int j = 0; j < 8; j++) acc[i][j] += a[i] * bb[j];
        }
        __syncthreads();
    }

#pragma unroll
    for (int i = 0; i < 8; i++) {
        int gr = row0 + tr * 8 + i;
#pragma unroll
        for (int j = 0; j < 8; j++) {
            int gc = col0 + tc * 8 + j;
            out[(size_t)gr * DM + gc] = acc[i][j];
        }
    }
}

// ============================================================
// Prefill flash attention (causal). One block per (q-tile 64, head, batch).
// 256 threads. Scores 64x64 (4x4/thread), O 64x128 (4 rows x 8 cols/thread).
// Dynamic smem: Qs(64x128) + KVs(64x128) + Ps(64x64) + 3*64 row stats.
// ============================================================
__global__ __launch_bounds__(256) void attn_kernel() {
    extern __shared__ float sm[];
    float* Qs  = sm;                    // 8192
    float* KVs = sm + 64 * 128;         // 8192
    float* Ps  = sm + 2 * 64 * 128;     // 4096
    float* mrow = Ps + 64 * 64;         // 64
    float* lrow = mrow + 64;            // 64
    float* arow = lrow + 64;            // 64

    const int tid = threadIdx.x;
    const int qt = blockIdx.x;
    const int n  = blockIdx.y;
    const int b  = blockIdx.z;
    const int tr = tid >> 4;   // 0..15 -> score rows tr*4..tr*4+3
    const int tc = tid & 15;   // 0..15 -> score cols tc*4..tc*4+3, O cols tc*8..

    // load Q tile (contiguous 64x128 block)
    {
        const float4* s4 = (const float4*)(g_Q + ((size_t)(b * NH + n) * SEQ + qt * 64) * HD);
        float4* d4 = (float4*)Qs;
        for (int i = tid; i < 2048; i += 256) d4[i] = s4[i];
    }
    if (tid < 64) { mrow[tid] = -1e30f; lrow[tid] = 0.f; }

    float acc[4][8];
#pragma unroll
    for (int i = 0; i < 4; i++)
#pragma unroll
        for (int j = 0; j < 8; j++) acc[i][j] = 0.f;

    for (int kt = 0; kt <= qt; kt++) {
        __syncthreads();  // protect KVs (prev V) and Ps reuse
        {
            const float4* s4 = (const float4*)(g_K + ((size_t)(b * NH + n) * SEQ + kt * 64) * HD);
            float4* d4 = (float4*)KVs;
            for (int i = tid; i < 2048; i += 256) d4[i] = s4[i];
        }
        __syncthreads();

        // scores s[i][j] = Q[tr*4+i] . K[tc*4+j]
        float s[4][4];
#pragma unroll
        for (int i = 0; i < 4; i++)
#pragma unroll
            for (int j = 0; j < 4; j++) s[i][j] = 0.f;

        for (int h = 0; h < 128; h += 4) {
            float4 q[4], k[4];
#pragma unroll
            for (int i = 0; i < 4; i++) q[i] = *(float4*)&Qs[(tr * 4 + i) * 128 + h];
#pragma unroll
            for (int j = 0; j < 4; j++) k[j] = *(float4*)&KVs[(tc * 4 + j) * 128 + h];
#pragma unroll
            for (int i = 0; i < 4; i++)
#pragma unroll
                for (int j = 0; j < 4; j++) {
                    s[i][j] += q[i].x * k[j].x + q[i].y * k[j].y +
                               q[i].z * k[j].z + q[i].w * k[j].w;
                }
        }

        // scale + causal mask (only diagonal tile)
#pragma unroll
        for (int i = 0; i < 4; i++)
#pragma unroll
            for (int j = 0; j < 4; j++) {
                float v = s[i][j] * SCALE;
                if (kt == qt && (tc * 4 + j) > (tr * 4 + i)) v = -1e30f;
                s[i][j] = v;
            }

        // row max across the 16-lane column group
        float tm[4];
#pragma unroll
        for (int i = 0; i < 4; i++)
            tm[i] = fmaxf(fmaxf(s[i][0], s[i][1]), fmaxf(s[i][2], s[i][3]));
#pragma unroll
        for (int off = 8; off; off >>= 1)
#pragma unroll
            for (int i = 0; i < 4; i++)
                tm[i] = fmaxf(tm[i], __shfl_xor_sync(0xffffffffu, tm[i], off));

        if (tc == 0) {
#pragma unroll
            for (int i = 0; i < 4; i++) {
                int r = tr * 4 + i;
                float om = mrow[r];
                float nm = fmaxf(om, tm[i]);
                arow[r] = __expf(om - nm);
                mrow[r] = nm;
            }
        }
        __syncwarp();

        // exp + write P + row sums
        float rs[4] = {0.f, 0.f, 0.f, 0.f};
#pragma unroll
        for (int i = 0; i < 4; i++) {
            int r = tr * 4 + i;
            float m = mrow[r];
#pragma unroll
            for (int j = 0; j < 4; j++) {
                float p = __expf(s[i][j] - m);
                Ps[r * 64 + tc * 4 + j] = p;
                rs[i] += p;
            }
        }
#pragma unroll
        for (int off = 8; off; off >>= 1)
#pragma unroll
            for (int i = 0; i < 4; i++)
                rs[i] += __shfl_xor_sync(0xffffffffu, rs[i], off);
        if (tc == 0) {
#pragma unroll
            for (int i = 0; i < 4; i++) {
                int r = tr * 4 + i;
                lrow[r] = lrow[r] * arow[r] + rs[i];
            }
        }

        // rescale O
#pragma unroll
        for (int i = 0; i < 4; i++) {
            float al = arow[tr * 4 + i];
#pragma unroll
            for (int j = 0; j < 8; j++) acc[i][j] *= al;
        }

        __syncthreads();  // P written; done reading K -> load V over KVs
        {
            const float4* s4 = (const float4*)(g_V + ((size_t)(b * NH + n) * SEQ + kt * 64) * HD);
            float4* d4 = (float4*)KVs;
            for (int i = tid; i < 2048; i += 256) d4[i] = s4[i];
        }
        __syncthreads();

        // O += P @ V
        for (int k = 0; k < 64; k++) {
            float p[4];
#pragma unroll
            for (int i = 0; i < 4; i++) p[i] = Ps[(tr * 4 + i) * 64 + k];
            float4 v0 = *(float4*)&KVs[k * 128 + tc * 8];
            float4 v1 = *(float4*)&KVs[k * 128 + tc * 8 + 4];
            float vv[8] = {v0.x, v0.y, v0.z, v0.w, v1.x, v1.y, v1.z, v1.w};
#pragma unroll
            for (int i = 0; i < 4; i++)
#pragma unroll
                for (int j = 0; j < 8; j++) acc[i][j] += p[i] * vv[j];
        }
    }

    // normalize + store to g_ATT [B,S,N,H]
#pragma unroll
    for (int i = 0; i < 4; i++) {
        int r = tr * 4 + i;
        float inv = 1.f / lrow[r];
        size_t base = (size_t)(b * SEQ + qt * 64 + r) * NHD + n * HD + tc * 8;
#pragma unroll
        for (int j = 0; j < 8; j++) g_ATT[base + j] = acc[i][j] * inv;
    }
}

// ============================================================
// Decode: q1/k1/v1 projections.  grid (NH, 3, B), 128 threads.
// ============================================================
__global__ __launch_bounds__(128) void dec_proj_kernel(const float* __restrict__ xnew,
                                                       const float* __restrict__ wq,
                                                       const float* __restrict__ wk,
                                                       const float* __restrict__ wv) {
    __shared__ float xs[DM];
    const int n = blockIdx.x, p = blockIdx.y, b = blockIdx.z;
    const float* w = (p == 0) ? wq : ((p == 1) ? wk : wv);
    float* o = (p == 0) ? g_q1 : ((p == 1) ? g_k1 : g_v1);

    for (int i = threadIdx.x; i < DM; i += 128) xs[i] = xnew[(size_t)b * DM + i];
    __syncthreads();

    const int h = threadIdx.x;
    float acc = 0.f;
#pragma unroll 4
    for (int d = 0; d < DM; d++) acc += xs[d] * w[(size_t)d * NHD + n * HD + h];
    o[(b * NH + n) * HD + h] = acc;
}

// ============================================================
// Decode attention over S+1 tokens. grid (NH, B), 256 threads.
// ============================================================
__global__ __launch_bounds__(256) void dec_attn_kernel() {
    __shared__ float qs[HD];
    __shared__ float pr[SEQ + 1];
    __shared__ float rbuf[256];
    const int n = blockIdx.x, b = blockIdx.y;
    const int tid = threadIdx.x;

    if (tid < HD) qs[tid] = g_q1[(b * NH + n) * HD + tid];
    __syncthreads();

    float lmax = -1e30f;
    for (int t = tid; t < SEQ + 1; t += 256) {
        const float* kv = (t < SEQ) ? &g_K[((size_t)(b * NH + n) * SEQ + t) * HD]
                                    : &g_k1[(b * NH + n) * HD];
        float sc = 0.f;
#pragma unroll 4
        for (int h = 0; h < HD; h++) sc += qs[h] * kv[h];
        sc *= SCALE;
        pr[t] = sc;
        lmax = fmaxf(lmax, sc);
    }
    rbuf[tid] = lmax;
    __syncthreads();
    for (int off = 128; off; off >>= 1) {
        if (tid < off) rbuf[tid] = fmaxf(rbuf[tid], rbuf[tid + off]);
        __syncthreads();
    }
    const float m = rbuf[0];
    __syncthreads();

    float ls = 0.f;
    for (int t = tid; t < SEQ + 1; t += 256) {
        float p = __expf(pr[t] - m);
        pr[t] = p;
        ls += p;
    }
    rbuf[tid] = ls;
    __syncthreads();
    for (int off = 128; off; off >>= 1) {
        if (tid < off) rbuf[tid] += rbuf[tid + off];
        __syncthreads();
    }
    const float linv = 1.f / rbuf[0];

    if (tid < HD) {
        const float* Vb = &g_V[(size_t)(b * NH + n) * SEQ * HD];
        float o = 0.f;
#pragma unroll 4
        for (int t = 0; t < SEQ; t++) o += pr[t] * Vb[(size_t)t * HD + tid];
        o += pr[SEQ] * g_v1[(b * NH + n) * HD + tid];
        g_att1[(b * NH + n) * HD + tid] = o * linv;
    }
}

// ============================================================
// Decode output projection: out[b,d] = sum_k att1[b,k] * wo[d,k]
// grid (DM/8, B), 256 threads (8 warps, 1 d per warp).
// ============================================================
__global__ __launch_bounds__(256) void dec_outproj_kernel(const float* __restrict__ wo,
                                                          float* __restrict__ out) {
    __shared__ float as_[NHD];
    const int b = blockIdx.y;
    for (int i = threadIdx.x; i < NHD; i += 256) as_[i] = g_att1[b * NHD + i];
    __syncthreads();

    const int w = threadIdx.x >> 5;
    const int lane = threadIdx.x & 31;
    const int d = blockIdx.x * 8 + w;
    float acc = 0.f;
    for (int k = lane; k < NHD; k += 32) acc += as_[k] * wo[(size_t)d * NHD + k];
#pragma unroll
    for (int off = 16; off; off >>= 1) acc += __shfl_xor_sync(0xffffffffu, acc, off);
    if (lane == 0) out[(size_t)b * DM + d] = acc;
}

// ============================================================
extern "C" void kernel_launch(void* const* d_in, const int* in_sizes, int n_in,
                              void* d_out, int out_size) {
    const float* x    = (const float*)d_in[0];
    const float* xnew = (const float*)d_in[1];
    const float* wq   = (const float*)d_in[2];
    const float* wk   = (const float*)d_in[3];
    const float* wv   = (const float*)d_in[4];
    const float* wo   = (const float*)d_in[5];
    float* out = (float*)d_out;

    const int attn_smem = (2 * 64 * 128 + 64 * 64 + 3 * 64) * 4;  // 82688
    cudaFuncSetAttribute(attn_kernel, cudaFuncAttributeMaxDynamicSharedMemorySize,
                         attn_smem);

    dim3 gproj(NHD / 128, (BATCH * SEQ) / 128);  // (16, 32)
    proj_kernel<<<gproj, 256>>>(x, wq, 0);
    proj_kernel<<<gproj, 256>>>(x, wk, 1);
    proj_kernel<<<gproj, 256>>>(x, wv, 2);

    dim3 gattn(SEQ / 64, NH, BATCH);             // (32, 16, 2)
    attn_kernel<<<gattn, 256, attn_smem>>>();

    dim3 gout(DM / 128, (BATCH * SEQ) / 128);    // (16, 32)
    outproj_kernel<<<gout, 256>>>(wo, out);

    dim3 gdp(NH, 3, BATCH);
    dec_proj_kernel<<<gdp, 128>>>(xnew, wq, wk, wv);

    dim3 gda(NH, BATCH);
    dec_attn_kernel<<<gda, 256>>>();

    dim3 gdo(DM / 8, BATCH);
    dec_outproj_kernel<<<gdo, 256>>>(wo, out + (size_t)BATCH * SEQ * DM);
}

// round 2
// speedup vs baseline: 3.4206x; 3.4206x over previous
#include <cuda_runtime.h>

// ---------------- problem constants ----------------
constexpr int BATCH = 2;
constexpr int SEQ   = 2048;
constexpr int DM    = 2048;   // d_model
constexpr int NH    = 16;     // heads
constexpr int HD    = 128;    // head dim
constexpr int NHD   = NH * HD; // 2048
constexpr float SCALE = 0.08838834764831845f; // 1/sqrt(128)

// ---------------- scratch (device globals; no allocations allowed) --------
__device__ float g_Q[(size_t)BATCH * NH * SEQ * HD];   // [B,N,S,H]
__device__ float g_K[(size_t)BATCH * NH * SEQ * HD];   // [B,N,S,H]
__device__ float g_V[(size_t)BATCH * NH * SEQ * HD];   // [B,N,S,H]
__device__ float g_ATT[(size_t)BATCH * SEQ * NH * HD]; // [B,S,N,H]
__device__ float g_q1[BATCH * NH * HD];
__device__ float g_k1[BATCH * NH * HD];
__device__ float g_v1[BATCH * NH * HD];
__device__ float g_att1[BATCH * NH * HD];

// ---------------- tf32 helpers ----------------
__device__ __forceinline__ unsigned f2t(float f) {
    unsigned u;
    asm("cvt.rna.tf32.f32 %0, %1;" : "=r"(u) : "f"(f));
    return u;
}

__device__ __forceinline__ void mma8(float c[4], const unsigned a[4], const unsigned b[2]) {
    asm volatile(
        "mma.sync.aligned.m16n8k8.row.col.f32.tf32.tf32.f32 "
        "{%0,%1,%2,%3},{%4,%5,%6,%7},{%8,%9},{%0,%1,%2,%3};\n"
        : "+f"(c[0]), "+f"(c[1]), "+f"(c[2]), "+f"(c[3])
        : "r"(a[0]), "r"(a[1]), "r"(a[2]), "r"(a[3]), "r"(b[0]), "r"(b[1]));
}

__device__ __forceinline__ uint4 cvt4(float4 v) {
    uint4 u;
    u.x = f2t(v.x); u.y = f2t(v.y); u.z = f2t(v.z); u.w = f2t(v.w);
    return u;
}

// ============================================================
// Projection GEMM (tf32 mma): out[b,n,s,h] = sum_d x[b,s,d]*w[d,n*H+h]
// 128x128 tile, 256 threads (8 warps = 2m x 4n), K-step 16, double buffered.
// ============================================================
__global__ __launch_bounds__(256) void proj_tc(const float* __restrict__ x,
                                               const float* __restrict__ w,
                                               int sel) {
    __shared__ unsigned As[2][128][20];   // [m][k], pad 20 -> conflict-free frags
    __shared__ unsigned Bs[2][16][136];   // [k][n], pad 136

    float* out = (sel == 0) ? g_Q : ((sel == 1) ? g_K : g_V);

    const int tid = threadIdx.x;
    const int warp = tid >> 5, lane = tid & 31;
    const int wm = (warp & 1) * 64;
    const int wn = (warp >> 1) * 32;
    const int row0 = blockIdx.y * 128;
    const int col0 = blockIdx.x * 128;
    const int r = lane >> 2, c = lane & 3;

    // load assignments
    const int ar = tid >> 2;            // A rows ar, ar+64
    const int ak = (tid & 3) * 4;       // A k offset
    const int bk = tid >> 5;            // B k rows bk, bk+8
    const int bn = (tid & 31) * 4;      // B n offset

    float acc[4][4][4];
#pragma unroll
    for (int mi = 0; mi < 4; mi++)
#pragma unroll
        for (int ni = 0; ni < 4; ni++)
#pragma unroll
            for (int j = 0; j < 4; j++) acc[mi][ni][j] = 0.f;

    const int nstage = DM / 16;

    // prologue: load stage 0
    {
        float4 a0 = *(const float4*)(x + (size_t)(row0 + ar) * DM + ak);
        float4 a1 = *(const float4*)(x + (size_t)(row0 + ar + 64) * DM + ak);
        float4 b0 = *(const float4*)(w + (size_t)bk * NHD + col0 + bn);
        float4 b1 = *(const float4*)(w + (size_t)(bk + 8) * NHD + col0 + bn);
        *(uint4*)&As[0][ar][ak] = cvt4(a0);
        *(uint4*)&As[0][ar + 64][ak] = cvt4(a1);
        *(uint4*)&Bs[0][bk][bn] = cvt4(b0);
        *(uint4*)&Bs[0][bk + 8][bn] = cvt4(b1);
    }
    __syncthreads();

    for (int s = 0; s < nstage; s++) {
        const int buf = s & 1;
        float4 a0, a1, b0, b1;
        const bool pf = (s + 1 < nstage);
        if (pf) {
            const int k0 = (s + 1) * 16;
            a0 = *(const float4*)(x + (size_t)(row0 + ar) * DM + k0 + ak);
            a1 = *(const float4*)(x + (size_t)(row0 + ar + 64) * DM + k0 + ak);
            b0 = *(const float4*)(w + (size_t)(k0 + bk) * NHD + col0 + bn);
            b1 = *(const float4*)(w + (size_t)(k0 + bk + 8) * NHD + col0 + bn);
        }

#pragma unroll
        for (int ks = 0; ks < 16; ks += 8) {
            unsigned af[4][4], bf[4][2];
#pragma unroll
            for (int mi = 0; mi < 4; mi++) {
                const int m = wm + mi * 16;
                af[mi][0] = As[buf][m + r][ks + c];
                af[mi][1] = As[buf][m + r + 8][ks + c];
                af[mi][2] = As[buf][m + r][ks + c + 4];
                af[mi][3] = As[buf][m + r + 8][ks + c + 4];
            }
#pragma unroll
            for (int ni = 0; ni < 4; ni++) {
                const int nn = wn + ni * 8;
                bf[ni][0] = Bs[buf][ks + c][nn + r];
                bf[ni][1] = Bs[buf][ks + c + 4][nn + r];
            }
#pragma unroll
            for (int mi = 0; mi < 4; mi++)
#pragma unroll
                for (int ni = 0; ni < 4; ni++) mma8(acc[mi][ni], af[mi], bf[ni]);
        }

        if (pf) {
            *(uint4*)&As[buf ^ 1][ar][ak] = cvt4(a0);
            *(uint4*)&As[buf ^ 1][ar + 64][ak] = cvt4(a1);
            *(uint4*)&Bs[buf ^ 1][bk][bn] = cvt4(b0);
            *(uint4*)&Bs[buf ^ 1][bk + 8][bn] = cvt4(b1);
        }
        __syncthreads();
    }

    // store into [B,N,S,H]
#pragma unroll
    for (int mi = 0; mi < 4; mi++) {
        const int gr0 = row0 + wm + mi * 16 + r;
        const int gr1 = gr0 + 8;
#pragma unroll
        for (int ni = 0; ni < 4; ni++) {
            const int gc = col0 + wn + ni * 8 + c * 2;
            const int nn = gc >> 7, hh = gc & 127;
            size_t base0 = (((size_t)(gr0 >> 11) * NH + nn) * SEQ + (gr0 & (SEQ - 1))) * HD + hh;
            size_t base1 = (((size_t)(gr1 >> 11) * NH + nn) * SEQ + (gr1 & (SEQ - 1))) * HD + hh;
            *(float2*)(out + base0) = make_float2(acc[mi][ni][0], acc[mi][ni][1]);
            *(float2*)(out + base1) = make_float2(acc[mi][ni][2], acc[mi][ni][3]);
        }
    }
}

// ============================================================
// Output projection (NT, tf32 mma): out[row,d] = sum_k A[row,k]*wo[d,k]
// ============================================================
__global__ __launch_bounds__(256) void outproj_tc(const float* __restrict__ wo,
                                                  float* __restrict__ out) {
    __shared__ unsigned As[2][128][20];
    __shared__ unsigned Bs[2][16][136];

    const float* A = g_ATT;
    const int tid = threadIdx.x;
    const int warp = tid >> 5, lane = tid & 31;
    const int wm = (warp & 1) * 64;
    const int wn = (warp >> 1) * 32;
    const int row0 = blockIdx.y * 128;
    const int col0 = blockIdx.x * 128;
    const int r = lane >> 2, c = lane & 3;

    const int ar = tid >> 2;
    const int ak = (tid & 3) * 4;
    const int bnn = tid & 127;          // B: n index (d)
    const int bkq = (tid >> 7) * 4;     // k offsets bkq, bkq+8

    float acc[4][4][4];
#pragma unroll
    for (int mi = 0; mi < 4; mi++)
#pragma unroll
        for (int ni = 0; ni < 4; ni++)
#pragma unroll
            for (int j = 0; j < 4; j++) acc[mi][ni][j] = 0.f;

    const int nstage = NHD / 16;

    {
        float4 a0 = *(const float4*)(A + (size_t)(row0 + ar) * NHD + ak);
        float4 a1 = *(const float4*)(A + (size_t)(row0 + ar + 64) * NHD + ak);
        float4 b0 = *(const float4*)(wo + (size_t)(col0 + bnn) * NHD + bkq);
        float4 b1 = *(const float4*)(wo + (size_t)(col0 + bnn) * NHD + bkq + 8);
        *(uint4*)&As[0][ar][ak] = cvt4(a0);
        *(uint4*)&As[0][ar + 64][ak] = cvt4(a1);
        Bs[0][bkq + 0][bnn] = f2t(b0.x); Bs[0][bkq + 1][bnn] = f2t(b0.y);
        Bs[0][bkq + 2][bnn] = f2t(b0.z); Bs[0][bkq + 3][bnn] = f2t(b0.w);
        Bs[0][bkq + 8][bnn] = f2t(b1.x); Bs[0][bkq + 9][bnn] = f2t(b1.y);
        Bs[0][bkq + 10][bnn] = f2t(b1.z); Bs[0][bkq + 11][bnn] = f2t(b1.w);
    }
    __syncthreads();

    for (int s = 0; s < nstage; s++) {
        const int buf = s & 1;
        float4 a0, a1, b0, b1;
        const bool pf = (s + 1 < nstage);
        if (pf) {
            const int k0 = (s + 1) * 16;
            a0 = *(const float4*)(A + (size_t)(row0 + ar) * NHD + k0 + ak);
            a1 = *(const float4*)(A + (size_t)(row0 + ar + 64) * NHD + k0 + ak);
            b0 = *(const float4*)(wo + (size_t)(col0 + bnn) * NHD + k0 + bkq);
            b1 = *(const float4*)(wo + (size_t)(col0 + bnn) * NHD + k0 + bkq + 8);
        }

#pragma unroll
        for (int ks = 0; ks < 16; ks += 8) {
            unsigned af[4][4], bf[4][2];
#pragma unroll
            for (int mi = 0; mi < 4; mi++) {
                const int m = wm + mi * 16;
                af[mi][0] = As[buf][m + r][ks + c];
                af[mi][1] = As[buf][m + r + 8][ks + c];
                af[mi][2] = As[buf][m + r][ks + c + 4];
                af[mi][3] = As[buf][m + r + 8][ks + c + 4];
            }
#pragma unroll
            for (int ni = 0; ni < 4; ni++) {
                const int nn = wn + ni * 8;
                bf[ni][0] = Bs[buf][ks + c][nn + r];
                bf[ni][1] = Bs[buf][ks + c + 4][nn + r];
            }
#pragma unroll
            for (int mi = 0; mi < 4; mi++)
#pragma unroll
                for (int ni = 0; ni < 4; ni++) mma8(acc[mi][ni], af[mi], bf[ni]);
        }

        if (pf) {
            *(uint4*)&As[buf ^ 1][ar][ak] = cvt4(a0);
            *(uint4*)&As[buf ^ 1][ar + 64][ak] = cvt4(a1);
            Bs[buf ^ 1][bkq + 0][bnn] = f2t(b0.x); Bs[buf ^ 1][bkq + 1][bnn] = f2t(b0.y);
            Bs[buf ^ 1][bkq + 2][bnn] = f2t(b0.z); Bs[buf ^ 1][bkq + 3][bnn] = f2t(b0.w);
            Bs[buf ^ 1][bkq + 8][bnn] = f2t(b1.x); Bs[buf ^ 1][bkq + 9][bnn] = f2t(b1.y);
            Bs[buf ^ 1][bkq + 10][bnn] = f2t(b1.z); Bs[buf ^ 1][bkq + 11][bnn] = f2t(b1.w);
        }
        __syncthreads();
    }

#pragma unroll
    for (int mi = 0; mi < 4; mi++) {
        const int gr0 = row0 + wm + mi * 16 + r;
        const int gr1 = gr0 + 8;
#pragma unroll
        for (int ni = 0; ni < 4; ni++) {
            const int gc = col0 + wn + ni * 8 + c * 2;
            *(float2*)(out + (size_t)gr0 * DM + gc) = make_float2(acc[mi][ni][0], acc[mi][ni][1]);
            *(float2*)(out + (size_t)gr1 * DM + gc) = make_float2(acc[mi][ni][2], acc[mi][ni][3]);
        }
    }
}

// ============================================================
// Prefill flash attention, tf32 mma. 64-row q tiles, 256 threads/8 warps.
// warp_m = warp&3 (16 rows), warp_n = warp>>2 (S: 32 cols, O: 64 dims).
// ============================================================
__global__ __launch_bounds__(256) void attn_tc() {
    extern __shared__ float sm[];
    unsigned* Qsu  = (unsigned*)sm;                  // 64 x 136 (tf32)
    unsigned* KVsu = Qsu + 64 * 136;                 // 64 x 136 (tf32)
    unsigned* Psu  = KVsu + 64 * 136;                // 64 x 68  (tf32)
    float* mrow = (float*)(Psu + 64 * 68);           // 64
    float* lrow = mrow + 64;                         // 64
    float* wm_s = lrow + 64;                         // 2 x 64
    float* ws_s = wm_s + 128;                        // 2 x 64

    const int tid = threadIdx.x;
    const int warp = tid >> 5, lane = tid & 31;
    const int wmi = warp & 3;      // row tile: rows wmi*16 .. +15
    const int wni = warp >> 2;     // 0..1
    const int r = lane >> 2, c = lane & 3;

    const int qt = gridDim.x - 1 - blockIdx.x;   // heavy tiles first
    const int n = blockIdx.y;
    const int b = blockIdx.z;

    const size_t headbase = ((size_t)(b * NH + n)) * SEQ * HD;

    // load Q tile (tf32)
    {
        const float* src = g_Q + headbase + (size_t)qt * 64 * HD;
        for (int i = tid; i < 2048; i += 256) {
            int row = i >> 5, c4 = (i & 31) * 4;
            float4 v = *(const float4*)(src + row * HD + c4);
            *(uint4*)&Qsu[row * 136 + c4] = cvt4(v);
        }
    }
    if (tid < 64) { mrow[tid] = -1e30f; lrow[tid] = 0.f; }

    float acc_o[8][4];
#pragma unroll
    for (int j = 0; j < 8; j++)
#pragma unroll
        for (int k = 0; k < 4; k++) acc_o[j][k] = 0.f;

    const int row_l0 = wmi * 16 + r;       // local rows this thread owns
    const int row_l1 = row_l0 + 8;

    for (int kt = 0; kt <= qt; kt++) {
        __syncthreads();   // prev V reads / init done before overwriting KVs
        {
            const float* src = g_K + headbase + (size_t)kt * 64 * HD;
            for (int i = tid; i < 2048; i += 256) {
                int row = i >> 5, c4 = (i & 31) * 4;
                float4 v = *(const float4*)(src + row * HD + c4);
                *(uint4*)&KVsu[row * 136 + c4] = cvt4(v);
            }
        }
        __syncthreads();

        // ---- S = Q K^T (64x64), this warp: rows wmi*16.., cols wni*32.. ----
        float sacc[4][4];
#pragma unroll
        for (int ni = 0; ni < 4; ni++)
#pragma unroll
            for (int j = 0; j < 4; j++) sacc[ni][j] = 0.f;

#pragma unroll
        for (int k0 = 0; k0 < 128; k0 += 8) {
            unsigned af[4];
            af[0] = Qsu[row_l0 * 136 + k0 + c];
            af[1] = Qsu[row_l1 * 136 + k0 + c];
            af[2] = Qsu[row_l0 * 136 + k0 + c + 4];
            af[3] = Qsu[row_l1 * 136 + k0 + c + 4];
#pragma unroll
            for (int ni = 0; ni < 4; ni++) {
                const int tok = wni * 32 + ni * 8 + r;
                unsigned bf[2];
                bf[0] = KVsu[tok * 136 + k0 + c];
                bf[1] = KVsu[tok * 136 + k0 + c + 4];
                mma8(sacc[ni], af, bf);
            }
        }

        // scale + causal mask
        const int grow0 = qt * 64 + row_l0;
        const int grow1 = qt * 64 + row_l1;
#pragma unroll
        for (int ni = 0; ni < 4; ni++) {
            const int gcol = kt * 64 + wni * 32 + ni * 8 + c * 2;
            sacc[ni][0] = (gcol     <= grow0) ? sacc[ni][0] * SCALE : -1e30f;
            sacc[ni][1] = (gcol + 1 <= grow0) ? sacc[ni][1] * SCALE : -1e30f;
            sacc[ni][2] = (gcol     <= grow1) ? sacc[ni][2] * SCALE : -1e30f;
            sacc[ni][3] = (gcol + 1 <= grow1) ? sacc[ni][3] * SCALE : -1e30f;
        }

        // warp-level row max (over 32 cols this warp owns)
        float m0 = -1e30f, m1 = -1e30f;
#pragma unroll
        for (int ni = 0; ni < 4; ni++) {
            m0 = fmaxf(m0, fmaxf(sacc[ni][0], sacc[ni][1]));
            m1 = fmaxf(m1, fmaxf(sacc[ni][2], sacc[ni][3]));
        }
        m0 = fmaxf(m0, __shfl_xor_sync(0xffffffffu, m0, 1));
        m0 = fmaxf(m0, __shfl_xor_sync(0xffffffffu, m0, 2));
        m1 = fmaxf(m1, __shfl_xor_sync(0xffffffffu, m1, 1));
        m1 = fmaxf(m1, __shfl_xor_sync(0xffffffffu, m1, 2));
        if (c == 0) { wm_s[wni * 64 + row_l0] = m0; wm_s[wni * 64 + row_l1] = m1; }
        __syncthreads();

        const float om0 = mrow[row_l0];
        const float nm0 = fmaxf(om0, fmaxf(wm_s[row_l0], wm_s[64 + row_l0]));
        const float al0 = __expf(om0 - nm0);
        const float om1 = mrow[row_l1];
        const float nm1 = fmaxf(om1, fmaxf(wm_s[row_l1], wm_s[64 + row_l1]));
        const float al1 = __expf(om1 - nm1);

        // P = exp(s - m), write tf32 P, row sums
        float s0 = 0.f, s1 = 0.f;
#pragma unroll
        for (int ni = 0; ni < 4; ni++) {
            const int col = wni * 32 + ni * 8 + c * 2;
            float p00 = __expf(sacc[ni][0] - nm0);
            float p01 = __expf(sacc[ni][1] - nm0);
            float p10 = __expf(sacc[ni][2] - nm1);
            float p11 = __expf(sacc[ni][3] - nm1);
            s0 += p00 + p01;
            s1 += p10 + p11;
            Psu[row_l0 * 68 + col]     = f2t(p00);
            Psu[row_l0 * 68 + col + 1] = f2t(p01);
            Psu[row_l1 * 68 + col]     = f2t(p10);
            Psu[row_l1 * 68 + col + 1] = f2t(p11);
        }
        s0 += __shfl_xor_sync(0xffffffffu, s0, 1);
        s0 += __shfl_xor_sync(0xffffffffu, s0, 2);
        s1 += __shfl_xor_sync(0xffffffffu, s1, 1);
        s1 += __shfl_xor_sync(0xffffffffu, s1, 2);
        if (c == 0) { ws_s[wni * 64 + row_l0] = s0; ws_s[wni * 64 + row_l1] = s1; }

        // rescale O accumulator
#pragma unroll
        for (int nj = 0; nj < 8; nj++) {
            acc_o[nj][0] *= al0; acc_o[nj][1] *= al0;
            acc_o[nj][2] *= al1; acc_o[nj][3] *= al1;
        }
        __syncthreads();   // P + ws written; K reads done

        // update global row stats (one thread per row)
        if (tid < 64) {
            const float om = mrow[tid];
            const float nm = fmaxf(om, fmaxf(wm_s[tid], wm_s[64 + tid]));
            lrow[tid] = lrow[tid] * __expf(om - nm) + ws_s[tid] + ws_s[64 + tid];
            mrow[tid] = nm;
        }

        // load V tile over KVs
        {
            const float* src = g_V + headbase + (size_t)kt * 64 * HD;
            for (int i = tid; i < 2048; i += 256) {
                int row = i >> 5, c4 = (i & 31) * 4;
                float4 v = *(const float4*)(src + row * HD + c4);
                *(uint4*)&KVsu[row * 136 + c4] = cvt4(v);
            }
        }
        __syncthreads();

        // ---- O += P V, this warp: rows wmi*16.., dims wni*64.. ----
#pragma unroll
        for (int k0 = 0; k0 < 64; k0 += 8) {
            unsigned af[4];
            af[0] = Psu[row_l0 * 68 + k0 + c];
            af[1] = Psu[row_l1 * 68 + k0 + c];
            af[2] = Psu[row_l0 * 68 + k0 + c + 4];
            af[3] = Psu[row_l1 * 68 + k0 + c + 4];
#pragma unroll
            for (int nj = 0; nj < 8; nj++) {
                const int dim = wni * 64 + nj * 8 + r;
                unsigned bf[2];
                bf[0] = KVsu[(k0 + c) * 136 + dim];
                bf[1] = KVsu[(k0 + c + 4) * 136 + dim];
                mma8(acc_o[nj], af, bf);
            }
        }
    }

    // normalize + store to g_ATT [B,S,N,H]
    const float inv0 = 1.f / lrow[row_l0];
    const float inv1 = 1.f / lrow[row_l1];
#pragma unroll
    for (int nj = 0; nj < 8; nj++) {
        const int dim = wni * 64 + nj * 8 + c * 2;
        size_t base0 = ((size_t)(b * SEQ + qt * 64 + row_l0)) * NHD + n * HD + dim;
        size_t base1 = ((size_t)(b * SEQ + qt * 64 + row_l1)) * NHD + n * HD + dim;
        *(float2*)(g_ATT + base0) = make_float2(acc_o[nj][0] * inv0, acc_o[nj][1] * inv0);
        *(float2*)(g_ATT + base1) = make_float2(acc_o[nj][2] * inv1, acc_o[nj][3] * inv1);
    }
}

// ============================================================
// Decode kernels (tiny; unchanged from R1)
// ============================================================
__global__ __launch_bounds__(128) void dec_proj_kernel(const float* __restrict__ xnew,
                                                       const float* __restrict__ wq,
                                                       const float* __restrict__ wk,
                                                       const float* __restrict__ wv) {
    __shared__ float xs[DM];
    const int n = blockIdx.x, p = blockIdx.y, b = blockIdx.z;
    const float* w = (p == 0) ? wq : ((p == 1) ? wk : wv);
    float* o = (p == 0) ? g_q1 : ((p == 1) ? g_k1 : g_v1);

    for (int i = threadIdx.x; i < DM; i += 128) xs[i] = xnew[(size_t)b * DM + i];
    __syncthreads();

    const int h = threadIdx.x;
    float acc = 0.f;
#pragma unroll 4
    for (int d = 0; d < DM; d++) acc += xs[d] * w[(size_t)d * NHD + n * HD + h];
    o[(b * NH + n) * HD + h] = acc;
}

__global__ __launch_bounds__(256) void dec_attn_kernel() {
    __shared__ float qs[HD];
    __shared__ float pr[SEQ + 1];
    __shared__ float rbuf[256];
    const int n = blockIdx.x, b = blockIdx.y;
    const int tid = threadIdx.x;

    if (tid < HD) qs[tid] = g_q1[(b * NH + n) * HD + tid];
    __syncthreads();

    float lmax = -1e30f;
    for (int t = tid; t < SEQ + 1; t += 256) {
        const float* kv = (t < SEQ) ? &g_K[((size_t)(b * NH + n) * SEQ + t) * HD]
                                    : &g_k1[(b * NH + n) * HD];
        float sc = 0.f;
#pragma unroll 4
        for (int h = 0; h < HD; h++) sc += qs[h] * kv[h];
        sc *= SCALE;
        pr[t] = sc;
        lmax = fmaxf(lmax, sc);
    }
    rbuf[tid] = lmax;
    __syncthreads();
    for (int off = 128; off; off >>= 1) {
        if (tid < off) rbuf[tid] = fmaxf(rbuf[tid], rbuf[tid + off]);
        __syncthreads();
    }
    const float m = rbuf[0];
    __syncthreads();

    float ls = 0.f;
    for (int t = tid; t < SEQ + 1; t += 256) {
        float p = __expf(pr[t] - m);
        pr[t] = p;
        ls += p;
    }
    rbuf[tid] = ls;
    __syncthreads();
    for (int off = 128; off; off >>= 1) {
        if (tid < off) rbuf[tid] += rbuf[tid + off];
        __syncthreads();
    }
    const float linv = 1.f / rbuf[0];

    if (tid < HD) {
        const float* Vb = &g_V[(size_t)(b * NH + n) * SEQ * HD];
        float o = 0.f;
#pragma unroll 4
        for (int t = 0; t < SEQ; t++) o += pr[t] * Vb[(size_t)t * HD + tid];
        o += pr[SEQ] * g_v1[(b * NH + n) * HD + tid];
        g_att1[(b * NH + n) * HD + tid] = o * linv;
    }
}

__global__ __launch_bounds__(256) void dec_outproj_kernel(const float* __restrict__ wo,
                                                          float* __restrict__ out) {
    __shared__ float as_[NHD];
    const int b = blockIdx.y;
    for (int i = threadIdx.x; i < NHD; i += 256) as_[i] = g_att1[b * NHD + i];
    __syncthreads();

    const int w = threadIdx.x >> 5;
    const int lane = threadIdx.x & 31;
    const int d = blockIdx.x * 8 + w;
    float acc = 0.f;
    for (int k = lane; k < NHD; k += 32) acc += as_[k] * wo[(size_t)d * NHD + k];
#pragma unroll
    for (int off = 16; off; off >>= 1) acc += __shfl_xor_sync(0xffffffffu, acc, off);
    if (lane == 0) out[(size_t)b * DM + d] = acc;
}

// ============================================================
extern "C" void kernel_launch(void* const* d_in, const int* in_sizes, int n_in,
                              void* d_out, int out_size) {
    const float* x    = (const float*)d_in[0];
    const float* xnew = (const float*)d_in[1];
    const float* wq   = (const float*)d_in[2];
    const float* wk   = (const float*)d_in[3];
    const float* wv   = (const float*)d_in[4];
    const float* wo   = (const float*)d_in[5];
    float* out = (float*)d_out;

    const int attn_smem = (64 * 136 * 2 + 64 * 68 + 64 * 2 + 128 * 2) * 4; // 88576
    static bool attr_set = false;
    if (!attr_set) {
        cudaFuncSetAttribute(attn_tc, cudaFuncAttributeMaxDynamicSharedMemorySize,
                             attn_smem);
        attr_set = true;
    }

    dim3 gproj(NHD / 128, (BATCH * SEQ) / 128);  // (16, 32)
    proj_tc<<<gproj, 256>>>(x, wq, 0);
    proj_tc<<<gproj, 256>>>(x, wk, 1);
    proj_tc<<<gproj, 256>>>(x, wv, 2);

    dim3 gattn(SEQ / 64, NH, BATCH);             // (32, 16, 2)
    attn_tc<<<gattn, 256, attn_smem>>>();

    dim3 gout(DM / 128, (BATCH * SEQ) / 128);    // (16, 32)
    outproj_tc<<<gout, 256>>>(wo, out);

    dim3 gdp(NH, 3, BATCH);
    dec_proj_kernel<<<gdp, 128>>>(xnew, wq, wk, wv);

    dim3 gda(NH, BATCH);
    dec_attn_kernel<<<gda, 256>>>();

    dim3 gdo(DM / 8, BATCH);
    dec_outproj_kernel<<<gdo, 256>>>(wo, out + (size_t)BATCH * SEQ * DM);
}

// round 3
// speedup vs baseline: 4.1993x; 1.2277x over previous
#include <cuda_runtime.h>

// ---------------- problem constants ----------------
constexpr int BATCH = 2;
constexpr int SEQ   = 2048;
constexpr int DM    = 2048;
constexpr int NH    = 16;
constexpr int HD    = 128;
constexpr int NHD   = NH * HD;
constexpr float SCALE = 0.08838834764831845f; // 1/sqrt(128)

// ---------------- scratch ----------------
__device__ float g_xt[(size_t)BATCH * SEQ * DM];       // tf32-rounded x
__device__ float g_wqt[(size_t)DM * NHD];
__device__ float g_wkt[(size_t)DM * NHD];
__device__ float g_wvt[(size_t)DM * NHD];
__device__ float g_wot[(size_t)DM * NHD];
__device__ float g_Q[(size_t)BATCH * NH * SEQ * HD];   // [B,N,S,H] tf32, pre-scaled
__device__ float g_K[(size_t)BATCH * NH * SEQ * HD];   // [B,N,S,H] tf32
__device__ float g_V[(size_t)BATCH * NH * SEQ * HD];   // [B,N,S,H] tf32
__device__ float g_ATT[(size_t)BATCH * SEQ * NH * HD]; // [B,S,N,H] tf32
__device__ float g_q1[BATCH * NH * HD];
__device__ float g_k1[BATCH * NH * HD];
__device__ float g_v1[BATCH * NH * HD];
__device__ float g_att1[BATCH * NH * HD];

// ---------------- helpers ----------------
__device__ __forceinline__ unsigned f2t(float f) {
    unsigned u;
    asm("cvt.rna.tf32.f32 %0, %1;" : "=r"(u) : "f"(f));
    return u;
}
__device__ __forceinline__ float f2tf(float f) { return __uint_as_float(f2t(f)); }

__device__ __forceinline__ void mma8(float c[4], const unsigned a[4], const unsigned b[2]) {
    asm volatile(
        "mma.sync.aligned.m16n8k8.row.col.f32.tf32.tf32.f32 "
        "{%0,%1,%2,%3},{%4,%5,%6,%7},{%8,%9},{%0,%1,%2,%3};\n"
        : "+f"(c[0]), "+f"(c[1]), "+f"(c[2]), "+f"(c[3])
        : "r"(a[0]), "r"(a[1]), "r"(a[2]), "r"(a[3]), "r"(b[0]), "r"(b[1]));
}

__device__ __forceinline__ void cpa16(float* dst_smem, const float* src) {
    unsigned d = (unsigned)__cvta_generic_to_shared(dst_smem);
    asm volatile("cp.async.cg.shared.global [%0], [%1], 16;\n" :: "r"(d), "l"(src));
}
__device__ __forceinline__ void cpa_commit() { asm volatile("cp.async.commit_group;\n"); }
template <int N> __device__ __forceinline__ void cpa_wait() {
    asm volatile("cp.async.wait_group %0;\n" ::"n"(N));
}

// ============================================================
// elementwise tf32 rounding: dst = tf32(src)
// ============================================================
__global__ __launch_bounds__(256) void cvt_kernel(const float* __restrict__ src,
                                                  float* __restrict__ dst, int n4) {
    int i = blockIdx.x * 256 + threadIdx.x;
    if (i < n4) {
        float4 v = ((const float4*)src)[i];
        v.x = f2tf(v.x); v.y = f2tf(v.y); v.z = f2tf(v.z); v.w = f2tf(v.w);
        ((float4*)dst)[i] = v;
    }
}

// ============================================================
// Fused QKV projection, tf32 mma, 3-stage cp.async.
// out[b,n,s,h] = sum_d x[b,s,d]*w[d,n*H+h], Q pre-scaled by SCALE.
// grid (16, 32, 3), block 256. smem dyn: As[3][128][20] + Bs[3][16][136].
// ============================================================
constexpr int PJ_AS = 128 * 20;   // per-stage A floats
constexpr int PJ_BS = 16 * 136;   // per-stage B floats
constexpr int PJ_SMEM = 3 * (PJ_AS + PJ_BS) * 4;

__global__ __launch_bounds__(256, 2) void proj_tc() {
    extern __shared__ float smp[];
    float* As = smp;                // [3][128][20]
    float* Bs = smp + 3 * PJ_AS;    // [3][16][136]

    const int sel = blockIdx.z;
    const float* a_src = g_xt;
    const float* b_src = (sel == 0) ? g_wqt : ((sel == 1) ? g_wkt : g_wvt);
    float* out = (sel == 0) ? g_Q : ((sel == 1) ? g_K : g_V);
    const float oscale = (sel == 0) ? SCALE : 1.0f;

    const int tid = threadIdx.x;
    const int warp = tid >> 5, lane = tid & 31;
    const int wm = (warp & 1) * 64;
    const int wn = (warp >> 1) * 32;
    const int row0 = blockIdx.y * 128;
    const int col0 = blockIdx.x * 128;
    const int r = lane >> 2, c = lane & 3;

    // load assignments (2 A chunks + 2 B chunks per thread per stage)
    const int a_row0 = tid >> 2;            // then +64
    const int a_kf = (tid & 3) * 4;
    const int b_row0 = tid >> 5;            // then +8
    const int b_nf = (lane) * 4;

    float acc[4][4][4];
#pragma unroll
    for (int mi = 0; mi < 4; mi++)
#pragma unroll
        for (int ni = 0; ni < 4; ni++)
#pragma unroll
            for (int j = 0; j < 4; j++) acc[mi][ni][j] = 0.f;

    const int nstage = DM / 16;

    auto load_stage = [&](int st, int k0) {
        float* A = As + st * PJ_AS;
        float* B = Bs + st * PJ_BS;
        cpa16(&A[a_row0 * 20 + a_kf], a_src + (size_t)(row0 + a_row0) * DM + k0 + a_kf);
        cpa16(&A[(a_row0 + 64) * 20 + a_kf], a_src + (size_t)(row0 + a_row0 + 64) * DM + k0 + a_kf);
        cpa16(&B[b_row0 * 136 + b_nf], b_src + (size_t)(k0 + b_row0) * NHD + col0 + b_nf);
        cpa16(&B[(b_row0 + 8) * 136 + b_nf], b_src + (size_t)(k0 + b_row0 + 8) * NHD + col0 + b_nf);
    };

    load_stage(0, 0); cpa_commit();
    load_stage(1, 16); cpa_commit();

    for (int s = 0; s < nstage; s++) {
        cpa_wait<1>();
        __syncthreads();
        if (s + 2 < nstage) load_stage((s + 2) % 3, (s + 2) * 16);
        cpa_commit();

        const unsigned* A = (const unsigned*)(As + (s % 3) * PJ_AS);
        const unsigned* B = (const unsigned*)(Bs + (s % 3) * PJ_BS);
#pragma unroll
        for (int ks = 0; ks < 16; ks += 8) {
            unsigned af[4][4], bf[4][2];
#pragma unroll
            for (int mi = 0; mi < 4; mi++) {
                const int m = wm + mi * 16;
                af[mi][0] = A[(m + r) * 20 + ks + c];
                af[mi][1] = A[(m + r + 8) * 20 + ks + c];
                af[mi][2] = A[(m + r) * 20 + ks + c + 4];
                af[mi][3] = A[(m + r + 8) * 20 + ks + c + 4];
            }
#pragma unroll
            for (int ni = 0; ni < 4; ni++) {
                const int nn = wn + ni * 8;
                bf[ni][0] = B[(ks + c) * 136 + nn + r];
                bf[ni][1] = B[(ks + c + 4) * 136 + nn + r];
            }
#pragma unroll
            for (int mi = 0; mi < 4; mi++)
#pragma unroll
                for (int ni = 0; ni < 4; ni++) mma8(acc[mi][ni], af[mi], bf[ni]);
        }
    }

    // store tf32-rounded into [B,N,S,H]
#pragma unroll
    for (int mi = 0; mi < 4; mi++) {
        const int gr0 = row0 + wm + mi * 16 + r;
        const int gr1 = gr0 + 8;
#pragma unroll
        for (int ni = 0; ni < 4; ni++) {
            const int gc = col0 + wn + ni * 8 + c * 2;
            const int nn = gc >> 7, hh = gc & 127;
            size_t base0 = (((size_t)(gr0 >> 11) * NH + nn) * SEQ + (gr0 & (SEQ - 1))) * HD + hh;
            size_t base1 = (((size_t)(gr1 >> 11) * NH + nn) * SEQ + (gr1 & (SEQ - 1))) * HD + hh;
            *(float2*)(out + base0) =
                make_float2(f2tf(acc[mi][ni][0] * oscale), f2tf(acc[mi][ni][1] * oscale));
            *(float2*)(out + base1) =
                make_float2(f2tf(acc[mi][ni][2] * oscale), f2tf(acc[mi][ni][3] * oscale));
        }
    }
}

// ============================================================
// Output projection (NT): out[row,d] = sum_k ATT[row,k]*wo[d,k]
// smem: As[3][128][20] + Bsd[3][128][20] (both [row][k]).
// ============================================================
constexpr int OP_TS = 128 * 20;
constexpr int OP_SMEM = 3 * 2 * OP_TS * 4;

__global__ __launch_bounds__(256, 2) void outproj_tc(float* __restrict__ out) {
    extern __shared__ float smp[];
    float* As = smp;                 // [3][128][20]
    float* Bsd = smp + 3 * OP_TS;    // [3][128][20]

    const float* a_src = g_ATT;
    const float* b_src = g_wot;

    const int tid = threadIdx.x;
    const int warp = tid >> 5, lane = tid & 31;
    const int wm = (warp & 1) * 64;
    const int wn = (warp >> 1) * 32;
    const int row0 = blockIdx.y * 128;
    const int col0 = blockIdx.x * 128;
    const int r = lane >> 2, c = lane & 3;

    const int a_row0 = tid >> 2;
    const int a_kf = (tid & 3) * 4;

    float acc[4][4][4];
#pragma unroll
    for (int mi = 0; mi < 4; mi++)
#pragma unroll
        for (int ni = 0; ni < 4; ni++)
#pragma unroll
            for (int j = 0; j < 4; j++) acc[mi][ni][j] = 0.f;

    const int nstage = NHD / 16;

    auto load_stage = [&](int st, int k0) {
        float* A = As + st * OP_TS;
        float* B = Bsd + st * OP_TS;
        cpa16(&A[a_row0 * 20 + a_kf], a_src + (size_t)(row0 + a_row0) * NHD + k0 + a_kf);
        cpa16(&A[(a_row0 + 64) * 20 + a_kf], a_src + (size_t)(row0 + a_row0 + 64) * NHD + k0 + a_kf);
        cpa16(&B[a_row0 * 20 + a_kf], b_src + (size_t)(col0 + a_row0) * NHD + k0 + a_kf);
        cpa16(&B[(a_row0 + 64) * 20 + a_kf], b_src + (size_t)(col0 + a_row0 + 64) * NHD + k0 + a_kf);
    };

    load_stage(0, 0); cpa_commit();
    load_stage(1, 16); cpa_commit();

    for (int s = 0; s < nstage; s++) {
        cpa_wait<1>();
        __syncthreads();
        if (s + 2 < nstage) load_stage((s + 2) % 3, (s + 2) * 16);
        cpa_commit();

        const unsigned* A = (const unsigned*)(As + (s % 3) * OP_TS);
        const unsigned* B = (const unsigned*)(Bsd + (s % 3) * OP_TS);
#pragma unroll
        for (int ks = 0; ks < 16; ks += 8) {
            unsigned af[4][4], bf[4][2];
#pragma unroll
            for (int mi = 0; mi < 4; mi++) {
                const int m = wm + mi * 16;
                af[mi][0] = A[(m + r) * 20 + ks + c];
                af[mi][1] = A[(m + r + 8) * 20 + ks + c];
                af[mi][2] = A[(m + r) * 20 + ks + c + 4];
                af[mi][3] = A[(m + r + 8) * 20 + ks + c + 4];
            }
#pragma unroll
            for (int ni = 0; ni < 4; ni++) {
                const int nn = wn + ni * 8;
                bf[ni][0] = B[(nn + r) * 20 + ks + c];
                bf[ni][1] = B[(nn + r) * 20 + ks + c + 4];
            }
#pragma unroll
            for (int mi = 0; mi < 4; mi++)
#pragma unroll
                for (int ni = 0; ni < 4; ni++) mma8(acc[mi][ni], af[mi], bf[ni]);
        }
    }

#pragma unroll
    for (int mi = 0; mi < 4; mi++) {
        const int gr0 = row0 + wm + mi * 16 + r;
        const int gr1 = gr0 + 8;
#pragma unroll
        for (int ni = 0; ni < 4; ni++) {
            const int gc = col0 + wn + ni * 8 + c * 2;
            *(float2*)(out + (size_t)gr0 * DM + gc) = make_float2(acc[mi][ni][0], acc[mi][ni][1]);
            *(float2*)(out + (size_t)gr1 * DM + gc) = make_float2(acc[mi][ni][2], acc[mi][ni][3]);
        }
    }
}

// ============================================================
// Prefill flash attention: 128-row Q tiles, 32-token K/V tiles,
// cp.async double-buffered, warp-local softmax (warp owns 16 rows).
// grid (16, NH, B), 256 threads.
// ============================================================
constexpr int QS = 132, KSTR = 132, VSTR = 136, PS = 36;
constexpr int AT_Q = 128 * QS;           // 16896
constexpr int AT_K = 32 * KSTR;          // 4224 per buf
constexpr int AT_V = 32 * VSTR;          // 4352 per buf
constexpr int AT_P = 128 * PS;           // 4608
constexpr int AT_SMEM = (AT_Q + 2 * AT_K + 2 * AT_V + AT_P) * 4; // 154624 B

__global__ __launch_bounds__(256) void attn_tc() {
    extern __shared__ float sm[];
    float* sQ = sm;
    float* sK = sQ + AT_Q;
    float* sV = sK + 2 * AT_K;
    float* sP = sV + 2 * AT_V;

    const int tid = threadIdx.x;
    const int warp = tid >> 5, lane = tid & 31;
    const int r = lane >> 2, c = lane & 3;

    const int qt = (gridDim.x - 1) - blockIdx.x;  // heavy tiles first
    const int n = blockIdx.y;
    const int b = blockIdx.z;

    const size_t headbase = ((size_t)(b * NH + n)) * SEQ * HD;
    const float* qsrc = g_Q + headbase + (size_t)qt * 128 * HD;
    const float* ksrc = g_K + headbase;
    const float* vsrc = g_V + headbase;

    const int row_l0 = warp * 16 + r;
    const int row_l1 = row_l0 + 8;
    const int grow0 = qt * 128 + row_l0;
    const int grow1 = grow0 + 8;
    const int nkt = (qt + 1) * 4;

    auto loadK = [&](int t, int buf) {
        float* dst = sK + buf * AT_K;
        const float* src = ksrc + (size_t)t * 32 * HD;
#pragma unroll
        for (int i = tid; i < 1024; i += 256) {
            int row = i >> 5, cf = (i & 31) * 4;
            cpa16(&dst[row * KSTR + cf], src + row * HD + cf);
        }
    };
    auto loadV = [&](int t, int buf) {
        float* dst = sV + buf * AT_V;
        const float* src = vsrc + (size_t)t * 32 * HD;
#pragma unroll
        for (int i = tid; i < 1024; i += 256) {
            int row = i >> 5, cf = (i & 31) * 4;
            cpa16(&dst[row * VSTR + cf], src + row * HD + cf);
        }
    };

    // prologue: Q + K0 + V0 in group 0
#pragma unroll
    for (int i = tid; i < 4096; i += 256) {
        int row = i >> 5, cf = (i & 31) * 4;
        cpa16(&sQ[row * QS + cf], qsrc + row * HD + cf);
    }
    loadK(0, 0);
    loadV(0, 0);
    cpa_commit();

    float m0 = -1e30f, m1 = -1e30f, l0 = 0.f, l1 = 0.f;
    float acc_o[16][4];
#pragma unroll
    for (int j = 0; j < 16; j++)
#pragma unroll
        for (int k = 0; k < 4; k++) acc_o[j][k] = 0.f;

    for (int kt = 0; kt < nkt; kt++) {
        const int buf = kt & 1;
        cpa_wait<0>();
        __syncthreads();   // all warps done with buf^1 (PV of kt-1) and P reads

        if (kt + 1 < nkt) { loadK(kt + 1, buf ^ 1); loadV(kt + 1, buf ^ 1); }
        cpa_commit();

        // ---- S = Q K^T : this warp rows warp*16..+15, cols 0..31 ----
        const unsigned* Qu = (const unsigned*)sQ;
        const unsigned* Ku = (const unsigned*)(sK + buf * AT_K);
        float sacc[4][4];
#pragma unroll
        for (int ni = 0; ni < 4; ni++)
#pragma unroll
            for (int j = 0; j < 4; j++) sacc[ni][j] = 0.f;

#pragma unroll
        for (int k0 = 0; k0 < 128; k0 += 8) {
            unsigned af[4];
            af[0] = Qu[row_l0 * QS + k0 + c];
            af[1] = Qu[row_l1 * QS + k0 + c];
            af[2] = Qu[row_l0 * QS + k0 + c + 4];
            af[3] = Qu[row_l1 * QS + k0 + c + 4];
#pragma unroll
            for (int ni = 0; ni < 4; ni++) {
                const int tok = ni * 8 + r;
                unsigned bf[2];
                bf[0] = Ku[tok * KSTR + k0 + c];
                bf[1] = Ku[tok * KSTR + k0 + c + 4];
                mma8(sacc[ni], af, bf);
            }
        }

        // causal mask (Q pre-scaled; sacc is final score)
        const int colbase = kt * 32;
        if (colbase + 31 > qt * 128 + warp * 16) {   // tile not fully unmasked for this warp
#pragma unroll
            for (int ni = 0; ni < 4; ni++) {
                const int gcol = colbase + ni * 8 + c * 2;
                if (gcol > grow0) sacc[ni][0] = -1e30f;
                if (gcol + 1 > grow0) sacc[ni][1] = -1e30f;
                if (gcol > grow1) sacc[ni][2] = -1e30f;
                if (gcol + 1 > grow1) sacc[ni][3] = -1e30f;
            }
        }

        // warp-local softmax over 32 cols
        float tm0 = -1e30f, tm1 = -1e30f;
#pragma unroll
        for (int ni = 0; ni < 4; ni++) {
            tm0 = fmaxf(tm0, fmaxf(sacc[ni][0], sacc[ni][1]));
            tm1 = fmaxf(tm1, fmaxf(sacc[ni][2], sacc[ni][3]));
        }
        tm0 = fmaxf(tm0, __shfl_xor_sync(0xffffffffu, tm0, 1));
        tm0 = fmaxf(tm0, __shfl_xor_sync(0xffffffffu, tm0, 2));
        tm1 = fmaxf(tm1, __shfl_xor_sync(0xffffffffu, tm1, 1));
        tm1 = fmaxf(tm1, __shfl_xor_sync(0xffffffffu, tm1, 2));

        const float nm0 = fmaxf(m0, tm0);
        const float nm1 = fmaxf(m1, tm1);
        const float al0 = __expf(m0 - nm0);
        const float al1 = __expf(m1 - nm1);
        m0 = nm0; m1 = nm1;

        float s0 = 0.f, s1 = 0.f;
#pragma unroll
        for (int ni = 0; ni < 4; ni++) {
            const int col = ni * 8 + c * 2;
            float p00 = __expf(sacc[ni][0] - nm0);
            float p01 = __expf(sacc[ni][1] - nm0);
            float p10 = __expf(sacc[ni][2] - nm1);
            float p11 = __expf(sacc[ni][3] - nm1);
            s0 += p00 + p01;
            s1 += p10 + p11;
            *(float2*)&sP[row_l0 * PS + col] = make_float2(f2tf(p00), f2tf(p01));
            *(float2*)&sP[row_l1 * PS + col] = make_float2(f2tf(p10), f2tf(p11));
        }
        s0 += __shfl_xor_sync(0xffffffffu, s0, 1);
        s0 += __shfl_xor_sync(0xffffffffu, s0, 2);
        s1 += __shfl_xor_sync(0xffffffffu, s1, 1);
        s1 += __shfl_xor_sync(0xffffffffu, s1, 2);
        l0 = l0 * al0 + s0;
        l1 = l1 * al1 + s1;

#pragma unroll
        for (int nj = 0; nj < 16; nj++) {
            acc_o[nj][0] *= al0; acc_o[nj][1] *= al0;
            acc_o[nj][2] *= al1; acc_o[nj][3] *= al1;
        }

        __syncthreads();   // P visible to all warps (each warp uses only its own rows, but keep tidy)

        // ---- O += P V : this warp rows warp*16..+15, dims 0..127 ----
        const unsigned* Pu = (const unsigned*)sP;
        const unsigned* Vu = (const unsigned*)(sV + buf * AT_V);
#pragma unroll
        for (int k0 = 0; k0 < 32; k0 += 8) {
            unsigned af[4];
            af[0] = Pu[row_l0 * PS + k0 + c];
            af[1] = Pu[row_l1 * PS + k0 + c];
            af[2] = Pu[row_l0 * PS + k0 + c + 4];
            af[3] = Pu[row_l1 * PS + k0 + c + 4];
#pragma unroll
            for (int nj = 0; nj < 16; nj++) {
                const int dim = nj * 8 + r;
                unsigned bf[2];
                bf[0] = Vu[(k0 + c) * VSTR + dim];
                bf[1] = Vu[(k0 + c + 4) * VSTR + dim];
                mma8(acc_o[nj], af, bf);
            }
        }
    }

    // normalize + tf32-rounded store to g_ATT [B,S,N,H]
    const float inv0 = 1.f / l0;
    const float inv1 = 1.f / l1;
#pragma unroll
    for (int nj = 0; nj < 16; nj++) {
        const int dim = nj * 8 + c * 2;
        size_t base0 = ((size_t)(b * SEQ + qt * 128 + row_l0)) * NHD + n * HD + dim;
        size_t base1 = ((size_t)(b * SEQ + qt * 128 + row_l1)) * NHD + n * HD + dim;
        *(float2*)(g_ATT + base0) =
            make_float2(f2tf(acc_o[nj][0] * inv0), f2tf(acc_o[nj][1] * inv0));
        *(float2*)(g_ATT + base1) =
            make_float2(f2tf(acc_o[nj][2] * inv1), f2tf(acc_o[nj][3] * inv1));
    }
}

// ============================================================
// Decode kernels (unchanged)
// ============================================================
__global__ __launch_bounds__(128) void dec_proj_kernel(const float* __restrict__ xnew,
                                                       const float* __restrict__ wq,
                                                       const float* __restrict__ wk,
                                                       const float* __restrict__ wv) {
    __shared__ float xs[DM];
    const int n = blockIdx.x, p = blockIdx.y, b = blockIdx.z;
    const float* w = (p == 0) ? wq : ((p == 1) ? wk : wv);
    float* o = (p == 0) ? g_q1 : ((p == 1) ? g_k1 : g_v1);

    for (int i = threadIdx.x; i < DM; i += 128) xs[i] = xnew[(size_t)b * DM + i];
    __syncthreads();

    const int h = threadIdx.x;
    float acc = 0.f;
#pragma unroll 4
    for (int d = 0; d < DM; d++) acc += xs[d] * w[(size_t)d * NHD + n * HD + h];
    o[(b * NH + n) * HD + h] = acc;
}

__global__ __launch_bounds__(256) void dec_attn_kernel() {
    __shared__ float qs[HD];
    __shared__ float pr[SEQ + 1];
    __shared__ float rbuf[256];
    const int n = blockIdx.x, b = blockIdx.y;
    const int tid = threadIdx.x;

    if (tid < HD) qs[tid] = g_q1[(b * NH + n) * HD + tid];
    __syncthreads();

    float lmax = -1e30f;
    for (int t = tid; t < SEQ + 1; t += 256) {
        const float* kv = (t < SEQ) ? &g_K[((size_t)(b * NH + n) * SEQ + t) * HD]
                                    : &g_k1[(b * NH + n) * HD];
        float sc = 0.f;
#pragma unroll 4
        for (int h = 0; h < HD; h++) sc += qs[h] * kv[h];
        sc *= SCALE;
        pr[t] = sc;
        lmax = fmaxf(lmax, sc);
    }
    rbuf[tid] = lmax;
    __syncthreads();
    for (int off = 128; off; off >>= 1) {
        if (tid < off) rbuf[tid] = fmaxf(rbuf[tid], rbuf[tid + off]);
        __syncthreads();
    }
    const float m = rbuf[0];
    __syncthreads();

    float ls = 0.f;
    for (int t = tid; t < SEQ + 1; t += 256) {
        float p = __expf(pr[t] - m);
        pr[t] = p;
        ls += p;
    }
    rbuf[tid] = ls;
    __syncthreads();
    for (int off = 128; off; off >>= 1) {
        if (tid < off) rbuf[tid] += rbuf[tid + off];
        __syncthreads();
    }
    const float linv = 1.f / rbuf[0];

    if (tid < HD) {
        const float* Vb = &g_V[(size_t)(b * NH + n) * SEQ * HD];
        float o = 0.f;
#pragma unroll 4
        for (int t = 0; t < SEQ; t++) o += pr[t] * Vb[(size_t)t * HD + tid];
        o += pr[SEQ] * g_v1[(b * NH + n) * HD + tid];
        g_att1[(b * NH + n) * HD + tid] = o * linv;
    }
}

__global__ __launch_bounds__(256) void dec_outproj_kernel(const float* __restrict__ wo,
                                                          float* __restrict__ out) {
    __shared__ float as_[NHD];
    const int b = blockIdx.y;
    for (int i = threadIdx.x; i < NHD; i += 256) as_[i] = g_att1[b * NHD + i];
    __syncthreads();

    const int w = threadIdx.x >> 5;
    const int lane = threadIdx.x & 31;
    const int d = blockIdx.x * 8 + w;
    float acc = 0.f;
    for (int k = lane; k < NHD; k += 32) acc += as_[k] * wo[(size_t)d * NHD + k];
#pragma unroll
    for (int off = 16; off; off >>= 1) acc += __shfl_xor_sync(0xffffffffu, acc, off);
    if (lane == 0) out[(size_t)b * DM + d] = acc;
}

// ============================================================
extern "C" void kernel_launch(void* const* d_in, const int* in_sizes, int n_in,
                              void* d_out, int out_size) {
    const float* x    = (const float*)d_in[0];
    const float* xnew = (const float*)d_in[1];
    const float* wq   = (const float*)d_in[2];
    const float* wk   = (const float*)d_in[3];
    const float* wv   = (const float*)d_in[4];
    const float* wo   = (const float*)d_in[5];
    float* out = (float*)d_out;

    static bool attr_set = false;
    if (!attr_set) {
        cudaFuncSetAttribute(proj_tc, cudaFuncAttributeMaxDynamicSharedMemorySize, PJ_SMEM);
        cudaFuncSetAttribute(outproj_tc, cudaFuncAttributeMaxDynamicSharedMemorySize, OP_SMEM);
        cudaFuncSetAttribute(attn_tc, cudaFuncAttributeMaxDynamicSharedMemorySize, AT_SMEM);
        attr_set = true;
    }

    // device pointers to scratch
    float *p_xt, *p_wqt, *p_wkt, *p_wvt, *p_wot;
    cudaGetSymbolAddress((void**)&p_xt, g_xt);
    cudaGetSymbolAddress((void**)&p_wqt, g_wqt);
    cudaGetSymbolAddress((void**)&p_wkt, g_wkt);
    cudaGetSymbolAddress((void**)&p_wvt, g_wvt);
    cudaGetSymbolAddress((void**)&p_wot, g_wot);

    const int x4 = BATCH * SEQ * DM / 4;     // 1,048,576 * 2
    const int w4 = DM * NHD / 4;             // 1,048,576
    cvt_kernel<<<(x4 + 255) / 256, 256>>>(x, p_xt, x4);
    cvt_kernel<<<(w4 + 255) / 256, 256>>>(wq, p_wqt, w4);
    cvt_kernel<<<(w4 + 255) / 256, 256>>>(wk, p_wkt, w4);
    cvt_kernel<<<(w4 + 255) / 256, 256>>>(wv, p_wvt, w4);
    cvt_kernel<<<(w4 + 255) / 256, 256>>>(wo, p_wot, w4);

    dim3 gproj(NHD / 128, (BATCH * SEQ) / 128, 3);  // (16, 32, 3)
    proj_tc<<<gproj, 256, PJ_SMEM>>>();

    dim3 gattn(SEQ / 128, NH, BATCH);               // (16, 16, 2)
    attn_tc<<<gattn, 256, AT_SMEM>>>();

    dim3 gout(DM / 128, (BATCH * SEQ) / 128);       // (16, 32)
    outproj_tc<<<gout, 256, OP_SMEM>>>(out);

    dim3 gdp(NH, 3, BATCH);
    dec_proj_kernel<<<gdp, 128>>>(xnew, wq, wk, wv);

    dim3 gda(NH, BATCH);
    dec_attn_kernel<<<gda, 256>>>();

    dim3 gdo(DM / 8, BATCH);
    dec_outproj_kernel<<<gdo, 256>>>(wo, out + (size_t)BATCH * SEQ * DM);
}

// round 5
// speedup vs baseline: 4.2383x; 1.0093x over previous
#include <cuda_runtime.h>

// ---------------- problem constants ----------------
constexpr int BATCH = 2;
constexpr int SEQ   = 2048;
constexpr int DM    = 2048;
constexpr int NH    = 16;
constexpr int HD    = 128;
constexpr int NHD   = NH * HD;
constexpr float SCALE = 0.08838834764831845f; // 1/sqrt(128)

// ---------------- scratch ----------------
__device__ float g_xt[(size_t)BATCH * SEQ * DM];       // tf32(x)
__device__ float g_wqT[(size_t)DM * NHD];              // tf32(wq)^T  [col][d]
__device__ float g_wkT[(size_t)DM * NHD];
__device__ float g_wvT[(size_t)DM * NHD];
__device__ float g_wot[(size_t)DM * NHD];              // tf32(wo)    [d][k]
__device__ float g_Q[(size_t)BATCH * NH * SEQ * HD];   // [B,N,S,H] tf32, pre-scaled
__device__ float g_K[(size_t)BATCH * NH * SEQ * HD];   // [B,N,S,H] tf32
__device__ float g_V[(size_t)BATCH * NH * SEQ * HD];   // [B,N,S,H] tf32
__device__ float g_ATT[(size_t)BATCH * SEQ * NH * HD]; // [B,S,N,H] tf32
__device__ float g_q1[BATCH * NH * HD];
__device__ float g_k1[BATCH * NH * HD];
__device__ float g_v1[BATCH * NH * HD];
__device__ float g_att1[BATCH * NH * HD];

// ---------------- helpers ----------------
__device__ __forceinline__ unsigned f2t(float f) {
    unsigned u;
    asm("cvt.rna.tf32.f32 %0, %1;" : "=r"(u) : "f"(f));
    return u;
}
__device__ __forceinline__ float f2tf(float f) { return __uint_as_float(f2t(f)); }

__device__ __forceinline__ void mma8(float c[4], const unsigned a[4], const unsigned b[2]) {
    asm volatile(
        "mma.sync.aligned.m16n8k8.row.col.f32.tf32.tf32.f32 "
        "{%0,%1,%2,%3},{%4,%5,%6,%7},{%8,%9},{%0,%1,%2,%3};\n"
        : "+f"(c[0]), "+f"(c[1]), "+f"(c[2]), "+f"(c[3])
        : "r"(a[0]), "r"(a[1]), "r"(a[2]), "r"(a[3]), "r"(b[0]), "r"(b[1]));
}

// ldmatrix x4: four 8x4-float tiles (viewed as 8x8 b16) -> one reg/thread each
__device__ __forceinline__ void ldsm4(unsigned r[4], const float* p) {
    unsigned a = (unsigned)__cvta_generic_to_shared(p);
    asm volatile("ldmatrix.sync.aligned.m8n8.x4.shared.b16 {%0,%1,%2,%3}, [%4];\n"
                 : "=r"(r[0]), "=r"(r[1]), "=r"(r[2]), "=r"(r[3]) : "r"(a));
}

__device__ __forceinline__ void cpa16(float* dst_smem, const float* src) {
    unsigned d = (unsigned)__cvta_generic_to_shared(dst_smem);
    asm volatile("cp.async.cg.shared.global [%0], [%1], 16;\n" :: "r"(d), "l"(src));
}
__device__ __forceinline__ void cpa_commit() { asm volatile("cp.async.commit_group;\n"); }
template <int N> __device__ __forceinline__ void cpa_wait() {
    asm volatile("cp.async.wait_group %0;\n" ::"n"(N));
}

// ============================================================
// elementwise tf32 rounding: dst = tf32(src)
// ============================================================
__global__ __launch_bounds__(256) void cvt_kernel(const float* __restrict__ src,
                                                  float* __restrict__ dst, int n4) {
    int i = blockIdx.x * 256 + threadIdx.x;
    if (i < n4) {
        float4 v = ((const float4*)src)[i];
        v.x = f2tf(v.x); v.y = f2tf(v.y); v.z = f2tf(v.z); v.w = f2tf(v.w);
        ((float4*)dst)[i] = v;
    }
}

// ============================================================
// transpose + tf32: dst[c][d] = tf32(src[d][c]) for 2048x2048 wq/wk/wv
// grid (64, 64, 3), block (32, 8)
// ============================================================
__global__ __launch_bounds__(256) void cvtT_kernel(const float* __restrict__ wq,
                                                   const float* __restrict__ wk,
                                                   const float* __restrict__ wv) {
    __shared__ float t[32][33];
    const int z = blockIdx.z;
    const float* src = (z == 0) ? wq : ((z == 1) ? wk : wv);
    float* dst = (z == 0) ? g_wqT : ((z == 1) ? g_wkT : g_wvT);

    const int bx = blockIdx.x * 32;   // src col (c)
    const int by = blockIdx.y * 32;   // src row (d)
    const int x = bx + threadIdx.x;
#pragma unroll
    for (int i = threadIdx.y; i < 32; i += 8)
        t[i][threadIdx.x] = src[(size_t)(by + i) * NHD + x];
    __syncthreads();
    const int xo = by + threadIdx.x;
#pragma unroll
    for (int i = threadIdx.y; i < 32; i += 8)
        dst[(size_t)(bx + i) * DM + xo] = f2tf(t[threadIdx.x][i]);
}

// ============================================================
// Fused QKV projection (NT, tf32 mma + ldmatrix, 3-stage cp.async).
// A = g_xt [row][k], B = wT [col][k]. Q pre-scaled by SCALE.
// grid (16, 32, 3), block 256. smem: As[3][128][20] + Bs[3][128][20]
// ============================================================
constexpr int GT = 128 * 20;          // per-stage tile floats
constexpr int GEMM_SMEM = 3 * 2 * GT * 4;

__global__ __launch_bounds__(256, 2) void proj_tc() {
    extern __shared__ float smp[];
    float* As = smp;
    float* Bs = smp + 3 * GT;

    const int sel = blockIdx.z;
    const float* a_src = g_xt;
    const float* b_src = (sel == 0) ? g_wqT : ((sel == 1) ? g_wkT : g_wvT);
    float* out = (sel == 0) ? g_Q : ((sel == 1) ? g_K : g_V);
    const float oscale = (sel == 0) ? SCALE : 1.0f;

    const int tid = threadIdx.x;
    const int warp = tid >> 5, lane = tid & 31;
    const int wm = (warp & 1) * 64;
    const int wn = (warp >> 1) * 32;
    const int row0 = blockIdx.y * 128;
    const int col0 = blockIdx.x * 128;
    const int r = lane >> 2, c = lane & 3;

    // ldmatrix lane addressing
    const int lt = lane >> 3, ll = lane & 7;
    const int a_r = ((lt & 1) << 3) + ll;    // A: tile bit0 -> +8 rows
    const int a_c = (lt >> 1) << 2;          //    tile bit1 -> +4 cols
    const int b_r = ((lt >> 1) << 3) + ll;   // B: tile bit1 -> +8 rows
    const int b_c = (lt & 1) << 2;           //    tile bit0 -> +4 cols

    const int ld_row = tid >> 1;
    const int ld_cf = (tid & 1) * 8;

    float acc[4][4][4];
#pragma unroll
    for (int mi = 0; mi < 4; mi++)
#pragma unroll
        for (int ni = 0; ni < 4; ni++)
#pragma unroll
            for (int j = 0; j < 4; j++) acc[mi][ni][j] = 0.f;

    const int nstage = DM / 16;

    auto load_stage = [&](int st, int k0) {
        float* A = As + st * GT;
        float* B = Bs + st * GT;
        cpa16(&A[ld_row * 20 + ld_cf], a_src + (size_t)(row0 + ld_row) * DM + k0 + ld_cf);
        cpa16(&A[ld_row * 20 + ld_cf + 4], a_src + (size_t)(row0 + ld_row) * DM + k0 + ld_cf + 4);
        cpa16(&B[ld_row * 20 + ld_cf], b_src + (size_t)(col0 + ld_row) * DM + k0 + ld_cf);
        cpa16(&B[ld_row * 20 + ld_cf + 4], b_src + (size_t)(col0 + ld_row) * DM + k0 + ld_cf + 4);
    };

    load_stage(0, 0); cpa_commit();
    load_stage(1, 16); cpa_commit();

    for (int s = 0; s < nstage; s++) {
        cpa_wait<1>();
        __syncthreads();
        if (s + 2 < nstage) load_stage((s + 2) % 3, (s + 2) * 16);
        cpa_commit();

        const float* A = As + (s % 3) * GT;
        const float* B = Bs + (s % 3) * GT;
#pragma unroll
        for (int ks = 0; ks < 16; ks += 8) {
            unsigned af[4][4], bq[2][4];
#pragma unroll
            for (int mi = 0; mi < 4; mi++)
                ldsm4(af[mi], &A[(wm + mi * 16 + a_r) * 20 + ks + a_c]);
#pragma unroll
            for (int p = 0; p < 2; p++)
                ldsm4(bq[p], &B[(wn + p * 16 + b_r) * 20 + ks + b_c]);
#pragma unroll
            for (int mi = 0; mi < 4; mi++)
#pragma unroll
                for (int ni = 0; ni < 4; ni++)
                    mma8(acc[mi][ni], af[mi], &bq[ni >> 1][(ni & 1) * 2]);
        }
    }

    // store tf32-rounded into [B,N,S,H]
#pragma unroll
    for (int mi = 0; mi < 4; mi++) {
        const int gr0 = row0 + wm + mi * 16 + r;
        const int gr1 = gr0 + 8;
#pragma unroll
        for (int ni = 0; ni < 4; ni++) {
            const int gc = col0 + wn + ni * 8 + c * 2;
            const int nn = gc >> 7, hh = gc & 127;
            size_t base0 = (((size_t)(gr0 >> 11) * NH + nn) * SEQ + (gr0 & (SEQ - 1))) * HD + hh;
            size_t base1 = (((size_t)(gr1 >> 11) * NH + nn) * SEQ + (gr1 & (SEQ - 1))) * HD + hh;
            *(float2*)(out + base0) =
                make_float2(f2tf(acc[mi][ni][0] * oscale), f2tf(acc[mi][ni][1] * oscale));
            *(float2*)(out + base1) =
                make_float2(f2tf(acc[mi][ni][2] * oscale), f2tf(acc[mi][ni][3] * oscale));
        }
    }
}

// ============================================================
// Output projection (NT): out[row,d] = sum_k ATT[row,k]*wo[d,k]
// ============================================================
__global__ __launch_bounds__(256, 2) void outproj_tc(float* __restrict__ out) {
    extern __shared__ float smp[];
    float* As = smp;
    float* Bs = smp + 3 * GT;

    const float* a_src = g_ATT;
    const float* b_src = g_wot;

    const int tid = threadIdx.x;
    const int warp = tid >> 5, lane = tid & 31;
    const int wm = (warp & 1) * 64;
    const int wn = (warp >> 1) * 32;
    const int row0 = blockIdx.y * 128;
    const int col0 = blockIdx.x * 128;
    const int r = lane >> 2, c = lane & 3;

    const int lt = lane >> 3, ll = lane & 7;
    const int a_r = ((lt & 1) << 3) + ll;
    const int a_c = (lt >> 1) << 2;
    const int b_r = ((lt >> 1) << 3) + ll;
    const int b_c = (lt & 1) << 2;

    const int ld_row = tid >> 1;
    const int ld_cf = (tid & 1) * 8;

    float acc[4][4][4];
#pragma unroll
    for (int mi = 0; mi < 4; mi++)
#pragma unroll
        for (int ni = 0; ni < 4; ni++)
#pragma unroll
            for (int j = 0; j < 4; j++) acc[mi][ni][j] = 0.f;

    const int nstage = NHD / 16;

    auto load_stage = [&](int st, int k0) {
        float* A = As + st * GT;
        float* B = Bs + st * GT;
        cpa16(&A[ld_row * 20 + ld_cf], a_src + (size_t)(row0 + ld_row) * NHD + k0 + ld_cf);
        cpa16(&A[ld_row * 20 + ld_cf + 4], a_src + (size_t)(row0 + ld_row) * NHD + k0 + ld_cf + 4);
        cpa16(&B[ld_row * 20 + ld_cf], b_src + (size_t)(col0 + ld_row) * NHD + k0 + ld_cf);
        cpa16(&B[ld_row * 20 + ld_cf + 4], b_src + (size_t)(col0 + ld_row) * NHD + k0 + ld_cf + 4);
    };

    load_stage(0, 0); cpa_commit();
    load_stage(1, 16); cpa_commit();

    for (int s = 0; s < nstage; s++) {
        cpa_wait<1>();
        __syncthreads();
        if (s + 2 < nstage) load_stage((s + 2) % 3, (s + 2) * 16);
        cpa_commit();

        const float* A = As + (s % 3) * GT;
        const float* B = Bs + (s % 3) * GT;
#pragma unroll
        for (int ks = 0; ks < 16; ks += 8) {
            unsigned af[4][4], bq[2][4];
#pragma unroll
            for (int mi = 0; mi < 4; mi++)
                ldsm4(af[mi], &A[(wm + mi * 16 + a_r) * 20 + ks + a_c]);
#pragma unroll
            for (int p = 0; p < 2; p++)
                ldsm4(bq[p], &B[(wn + p * 16 + b_r) * 20 + ks + b_c]);
#pragma unroll
            for (int mi = 0; mi < 4; mi++)
#pragma unroll
                for (int ni = 0; ni < 4; ni++)
                    mma8(acc[mi][ni], af[mi], &bq[ni >> 1][(ni & 1) * 2]);
        }
    }

#pragma unroll
    for (int mi = 0; mi < 4; mi++) {
        const int gr0 = row0 + wm + mi * 16 + r;
        const int gr1 = gr0 + 8;
#pragma unroll
        for (int ni = 0; ni < 4; ni++) {
            const int gc = col0 + wn + ni * 8 + c * 2;
            *(float2*)(out + (size_t)gr0 * DM + gc) = make_float2(acc[mi][ni][0], acc[mi][ni][1]);
            *(float2*)(out + (size_t)gr1 * DM + gc) = make_float2(acc[mi][ni][2], acc[mi][ni][3]);
        }
    }
}

// ============================================================
// Prefill flash attention: 128-row Q tiles, 32-token K/V tiles,
// cp.async double-buffered, warp-local softmax, ldmatrix frags.
// grid (16, NH, B), 256 threads.
// ============================================================
constexpr int QS = 132, KSTR = 132, VSTR = 136, PS = 36;
constexpr int AT_Q = 128 * QS;
constexpr int AT_K = 32 * KSTR;
constexpr int AT_V = 32 * VSTR;
constexpr int AT_P = 128 * PS;
constexpr int AT_SMEM = (AT_Q + 2 * AT_K + 2 * AT_V + AT_P) * 4;

__global__ __launch_bounds__(256) void attn_tc() {
    extern __shared__ float sm[];
    float* sQ = sm;
    float* sK = sQ + AT_Q;
    float* sV = sK + 2 * AT_K;
    float* sP = sV + 2 * AT_V;

    const int tid = threadIdx.x;
    const int warp = tid >> 5, lane = tid & 31;
    const int r = lane >> 2, c = lane & 3;

    const int lt = lane >> 3, ll = lane & 7;
    const int a_r = ((lt & 1) << 3) + ll;
    const int a_c = (lt >> 1) << 2;
    const int b_r = ((lt >> 1) << 3) + ll;
    const int b_c = (lt & 1) << 2;

    const int qt = (gridDim.x - 1) - blockIdx.x;  // heavy tiles first
    const int n = blockIdx.y;
    const int b = blockIdx.z;

    const size_t headbase = ((size_t)(b * NH + n)) * SEQ * HD;
    const float* qsrc = g_Q + headbase + (size_t)qt * 128 * HD;
    const float* ksrc = g_K + headbase;
    const float* vsrc = g_V + headbase;

    const int row_l0 = warp * 16 + r;
    const int row_l1 = row_l0 + 8;
    const int grow0 = qt * 128 + row_l0;
    const int grow1 = grow0 + 8;
    const int nkt = (qt + 1) * 4;

    auto loadK = [&](int t, int buf) {
        float* dst = sK + buf * AT_K;
        const float* src = ksrc + (size_t)t * 32 * HD;
#pragma unroll
        for (int i = tid; i < 1024; i += 256) {
            int row = i >> 5, cf = (i & 31) * 4;
            cpa16(&dst[row * KSTR + cf], src + row * HD + cf);
        }
    };
    auto loadV = [&](int t, int buf) {
        float* dst = sV + buf * AT_V;
        const float* src = vsrc + (size_t)t * 32 * HD;
#pragma unroll
        for (int i = tid; i < 1024; i += 256) {
            int row = i >> 5, cf = (i & 31) * 4;
            cpa16(&dst[row * VSTR + cf], src + row * HD + cf);
        }
    };

#pragma unroll
    for (int i = tid; i < 4096; i += 256) {
        int row = i >> 5, cf = (i & 31) * 4;
        cpa16(&sQ[row * QS + cf], qsrc + row * HD + cf);
    }
    loadK(0, 0);
    loadV(0, 0);
    cpa_commit();

    float m0 = -1e30f, m1 = -1e30f, l0 = 0.f, l1 = 0.f;
    float acc_o[16][4];
#pragma unroll
    for (int j = 0; j < 16; j++)
#pragma unroll
        for (int k = 0; k < 4; k++) acc_o[j][k] = 0.f;

    for (int kt = 0; kt < nkt; kt++) {
        const int buf = kt & 1;
        cpa_wait<0>();
        __syncthreads();

        if (kt + 1 < nkt) { loadK(kt + 1, buf ^ 1); loadV(kt + 1, buf ^ 1); }
        cpa_commit();

        // ---- S = Q K^T : this warp rows warp*16..+15, cols 0..31 ----
        const float* Ksm = sK + buf * AT_K;
        float sacc[4][4];
#pragma unroll
        for (int ni = 0; ni < 4; ni++)
#pragma unroll
            for (int j = 0; j < 4; j++) sacc[ni][j] = 0.f;

#pragma unroll
        for (int k0 = 0; k0 < 128; k0 += 8) {
            unsigned af[4], bq[2][4];
            ldsm4(af, &sQ[(warp * 16 + a_r) * QS + k0 + a_c]);
            ldsm4(bq[0], &Ksm[(b_r) * KSTR + k0 + b_c]);
            ldsm4(bq[1], &Ksm[(16 + b_r) * KSTR + k0 + b_c]);
#pragma unroll
            for (int ni = 0; ni < 4; ni++)
                mma8(sacc[ni], af, &bq[ni >> 1][(ni & 1) * 2]);
        }

        // causal mask (Q pre-scaled; sacc is final score)
        const int colbase = kt * 32;
        if (colbase + 31 > qt * 128 + warp * 16) {
#pragma unroll
            for (int ni = 0; ni < 4; ni++) {
                const int gcol = colbase + ni * 8 + c * 2;
                if (gcol > grow0) sacc[ni][0] = -1e30f;
                if (gcol + 1 > grow0) sacc[ni][1] = -1e30f;
                if (gcol > grow1) sacc[ni][2] = -1e30f;
                if (gcol + 1 > grow1) sacc[ni][3] = -1e30f;
            }
        }

        // warp-local softmax over 32 cols
        float tm0 = -1e30f, tm1 = -1e30f;
#pragma unroll
        for (int ni = 0; ni < 4; ni++) {
            tm0 = fmaxf(tm0, fmaxf(sacc[ni][0], sacc[ni][1]));
            tm1 = fmaxf(tm1, fmaxf(sacc[ni][2], sacc[ni][3]));
        }
        tm0 = fmaxf(tm0, __shfl_xor_sync(0xffffffffu, tm0, 1));
        tm0 = fmaxf(tm0, __shfl_xor_sync(0xffffffffu, tm0, 2));
        tm1 = fmaxf(tm1, __shfl_xor_sync(0xffffffffu, tm1, 1));
        tm1 = fmaxf(tm1, __shfl_xor_sync(0xffffffffu, tm1, 2));

        const float nm0 = fmaxf(m0, tm0);
        const float nm1 = fmaxf(m1, tm1);
        const float al0 = __expf(m0 - nm0);
        const float al1 = __expf(m1 - nm1);
        m0 = nm0; m1 = nm1;

        float s0 = 0.f, s1 = 0.f;
#pragma unroll
        for (int ni = 0; ni < 4; ni++) {
            const int col = ni * 8 + c * 2;
            float p00 = __expf(sacc[ni][0] - nm0);
            float p01 = __expf(sacc[ni][1] - nm0);
            float p10 = __expf(sacc[ni][2] - nm1);
            float p11 = __expf(sacc[ni][3] - nm1);
            s0 += p00 + p01;
            s1 += p10 + p11;
            *(float2*)&sP[row_l0 * PS + col] = make_float2(f2tf(p00), f2tf(p01));
            *(float2*)&sP[row_l1 * PS + col] = make_float2(f2tf(p10), f2tf(p11));
        }
        s0 += __shfl_xor_sync(0xffffffffu, s0, 1);
        s0 += __shfl_xor_sync(0xffffffffu, s0, 2);
        s1 += __shfl_xor_sync(0xffffffffu, s1, 1);
        s1 += __shfl_xor_sync(0xffffffffu, s1, 2);
        l0 = l0 * al0 + s0;
        l1 = l1 * al1 + s1;

#pragma unroll
        for (int nj = 0; nj < 16; nj++) {
            acc_o[nj][0] *= al0; acc_o[nj][1] *= al0;
            acc_o[nj][2] *= al1; acc_o[nj][3] *= al1;
        }

        __syncwarp();   // P for this warp's rows written by this warp only

        // ---- O += P V : this warp rows warp*16..+15, dims 0..127 ----
        const unsigned* Vu = (const unsigned*)(sV + buf * AT_V);
#pragma unroll
        for (int k0 = 0; k0 < 32; k0 += 8) {
            unsigned af[4];
            ldsm4(af, &sP[(warp * 16 + a_r) * PS + k0 + a_c]);
#pragma unroll
            for (int nj = 0; nj < 16; nj++) {
                const int dim = nj * 8 + r;
                unsigned bf[2];
                bf[0] = Vu[(k0 + c) * VSTR + dim];
                bf[1] = Vu[(k0 + c + 4) * VSTR + dim];
                mma8(acc_o[nj], af, bf);
            }
        }
    }

    // normalize + tf32-rounded store to g_ATT [B,S,N,H]
    const float inv0 = 1.f / l0;
    const float inv1 = 1.f / l1;
#pragma unroll
    for (int nj = 0; nj < 16; nj++) {
        const int dim = nj * 8 + c * 2;
        size_t base0 = ((size_t)(b * SEQ + qt * 128 + row_l0)) * NHD + n * HD + dim;
        size_t base1 = ((size_t)(b * SEQ + qt * 128 + row_l1)) * NHD + n * HD + dim;
        *(float2*)(g_ATT + base0) =
            make_float2(f2tf(acc_o[nj][0] * inv0), f2tf(acc_o[nj][1] * inv0));
        *(float2*)(g_ATT + base1) =
            make_float2(f2tf(acc_o[nj][2] * inv1), f2tf(acc_o[nj][3] * inv1));
    }
}

// ============================================================
// Decode kernels (unchanged)
// ============================================================
__global__ __launch_bounds__(128) void dec_proj_kernel(const float* __restrict__ xnew,
                                                       const float* __restrict__ wq,
                                                       const float* __restrict__ wk,
                                                       const float* __restrict__ wv) {
    __shared__ float xs[DM];
    const int n = blockIdx.x, p = blockIdx.y, b = blockIdx.z;
    const float* w = (p == 0) ? wq : ((p == 1) ? wk : wv);
    float* o = (p == 0) ? g_q1 : ((p == 1) ? g_k1 : g_v1);

    for (int i = threadIdx.x; i < DM; i += 128) xs[i] = xnew[(size_t)b * DM + i];
    __syncthreads();

    const int h = threadIdx.x;
    float acc = 0.f;
#pragma unroll 4
    for (int d = 0; d < DM; d++) acc += xs[d] * w[(size_t)d * NHD + n * HD + h];
    o[(b * NH + n) * HD + h] = acc;
}

__global__ __launch_bounds__(256) void dec_attn_kernel() {
    __shared__ float qs[HD];
    __shared__ float pr[SEQ + 1];
    __shared__ float rbuf[256];
    const int n = blockIdx.x, b = blockIdx.y;
    const int tid = threadIdx.x;

    if (tid < HD) qs[tid] = g_q1[(b * NH + n) * HD + tid];
    __syncthreads();

    float lmax = -1e30f;
    for (int t = tid; t < SEQ + 1; t += 256) {
        const float* kv = (t < SEQ) ? &g_K[((size_t)(b * NH + n) * SEQ + t) * HD]
                                    : &g_k1[(b * NH + n) * HD];
        float sc = 0.f;
#pragma unroll 4
        for (int h = 0; h < HD; h++) sc += qs[h] * kv[h];
        sc *= SCALE;
        pr[t] = sc;
        lmax = fmaxf(lmax, sc);
    }
    rbuf[tid] = lmax;
    __syncthreads();
    for (int off = 128; off; off >>= 1) {
        if (tid < off) rbuf[tid] = fmaxf(rbuf[tid], rbuf[tid + off]);
        __syncthreads();
    }
    const float m = rbuf[0];
    __syncthreads();

    float ls = 0.f;
    for (int t = tid; t < SEQ + 1; t += 256) {
        float p = __expf(pr[t] - m);
        pr[t] = p;
        ls += p;
    }
    rbuf[tid] = ls;
    __syncthreads();
    for (int off = 128; off; off >>= 1) {
        if (tid < off) rbuf[tid] += rbuf[tid + off];
        __syncthreads();
    }
    const float linv = 1.f / rbuf[0];

    if (tid < HD) {
        const float* Vb = &g_V[(size_t)(b * NH + n) * SEQ * HD];
        float o = 0.f;
#pragma unroll 4
        for (int t = 0; t < SEQ; t++) o += pr[t] * Vb[(size_t)t * HD + tid];
        o += pr[SEQ] * g_v1[(b * NH + n) * HD + tid];
        g_att1[(b * NH + n) * HD + tid] = o * linv;
    }
}

__global__ __launch_bounds__(256) void dec_outproj_kernel(const float* __restrict__ wo,
                                                          float* __restrict__ out) {
    __shared__ float as_[NHD];
    const int b = blockIdx.y;
    for (int i = threadIdx.x; i < NHD; i += 256) as_[i] = g_att1[b * NHD + i];
    __syncthreads();

    const int w = threadIdx.x >> 5;
    const int lane = threadIdx.x & 31;
    const int d = blockIdx.x * 8 + w;
    float acc = 0.f;
    for (int k = lane; k < NHD; k += 32) acc += as_[k] * wo[(size_t)d * NHD + k];
#pragma unroll
    for (int off = 16; off; off >>= 1) acc += __shfl_xor_sync(0xffffffffu, acc, off);
    if (lane == 0) out[(size_t)b * DM + d] = acc;
}

// ============================================================
extern "C" void kernel_launch(void* const* d_in, const int* in_sizes, int n_in,
                              void* d_out, int out_size) {
    const float* x    = (const float*)d_in[0];
    const float* xnew = (const float*)d_in[1];
    const float* wq   = (const float*)d_in[2];
    const float* wk   = (const float*)d_in[3];
    const float* wv   = (const float*)d_in[4];
    const float* wo   = (const float*)d_in[5];
    float* out = (float*)d_out;

    static bool attr_set = false;
    if (!attr_set) {
        cudaFuncSetAttribute(proj_tc, cudaFuncAttributeMaxDynamicSharedMemorySize, GEMM_SMEM);
        cudaFuncSetAttribute(outproj_tc, cudaFuncAttributeMaxDynamicSharedMemorySize, GEMM_SMEM);
        cudaFuncSetAttribute(attn_tc, cudaFuncAttributeMaxDynamicSharedMemorySize, AT_SMEM);
        attr_set = true;
    }

    float *p_xt, *p_wot;
    cudaGetSymbolAddress((void**)&p_xt, g_xt);
    cudaGetSymbolAddress((void**)&p_wot, g_wot);

    const int x4 = BATCH * SEQ * DM / 4;
    const int w4 = DM * NHD / 4;
    cvt_kernel<<<(x4 + 255) / 256, 256>>>(x, p_xt, x4);
    cvt_kernel<<<(w4 + 255) / 256, 256>>>(wo, p_wot, w4);

    dim3 gT(64, 64, 3);
    cvtT_kernel<<<gT, dim3(32, 8)>>>(wq, wk, wv);

    dim3 gproj(NHD / 128, (BATCH * SEQ) / 128, 3);  // (16, 32, 3)
    proj_tc<<<gproj, 256, GEMM_SMEM>>>();

    dim3 gattn(SEQ / 128, NH, BATCH);               // (16, 16, 2)
    attn_tc<<<gattn, 256, AT_SMEM>>>();

    dim3 gout(DM / 128, (BATCH * SEQ) / 128);       // (16, 32)
    outproj_tc<<<gout, 256, GEMM_SMEM>>>(out);

    dim3 gdp(NH, 3, BATCH);
    dec_proj_kernel<<<gdp, 128>>>(xnew, wq, wk, wv);

    dim3 gda(NH, BATCH);
    dec_attn_kernel<<<gda, 256>>>();

    dim3 gdo(DM / 8, BATCH);
    dec_outproj_kernel<<<gdo, 256>>>(wo, out + (size_t)BATCH * SEQ * DM);
}